// round 13
// baseline (speedup 1.0000x reference)
#include <cuda_runtime.h>
#include <cuda_fp16.h>
#include <cstdint>

// ---------------------------------------------------------------------------
// Problem constants
// ---------------------------------------------------------------------------
#define NR 20000          // readings
#define NS 5000           // skills
#define DD 512            // embedding dim
#define NL 3              // layers
#define NR_P 20096        // NR padded to 128
#define NS_P 5120         // NS padded to 128
#define KR_P 20032        // NR padded to 64 (K dim of A^T GEMM)
#define COL_CHUNKS 16
#define KSPLIT_R 4        // split-K for A@gs   (grid 2*157*4 = 1256)
#define KSPLIT_S 16       // split-K for A^T@gr (grid 2*40*16 = 1280)

// ---------------------------------------------------------------------------
// Device scratch (no cudaMalloc allowed)
// ---------------------------------------------------------------------------
__device__ float g_invdeg_r[NR];
__device__ float g_invdeg_s[NS];
__device__ float g_colpart[COL_CHUNKS * NS];

__device__ __align__(16) __half g_Ahi[(size_t)NR_P * NS_P];
__device__ __align__(16) __half g_hrhi[(size_t)NR_P * DD];
__device__ __align__(16) __half g_hrlo[(size_t)NR_P * DD];
__device__ __align__(16) __half g_hshi[(size_t)NS_P * DD];
__device__ __align__(16) __half g_gshi[(size_t)NS_P * DD];
__device__ __align__(16) __half g_grhi[(size_t)NR_P * DD];
__device__ __align__(16) __half g_WShi[(size_t)NL * DD * 1024];  // [Ws|Vs] hi
__device__ __align__(16) __half g_Wrhi[(size_t)NL * DD * DD];
__device__ __align__(16) __half g_Wrlo[(size_t)NL * DD * DD];
__device__ __align__(16) __half g_Vrhi[(size_t)NL * DD * DD];

__device__ float g_fS[(size_t)NS * 1024];            // [gs | ts]
__device__ float g_tr[(size_t)NR * DD];
__device__ float g_partR[(size_t)KSPLIT_R * NR * DD];
__device__ float g_partS[(size_t)KSPLIT_S * NS * DD];

// ---------------------------------------------------------------------------
// PTX helpers (Ampere-era ISA: compiles for plain compute_103 target)
// ---------------------------------------------------------------------------
__device__ __forceinline__ uint32_t smem_u32(const void* p) {
    uint32_t a;
    asm("{ .reg .u64 t; cvta.to.shared.u64 t, %1; cvt.u32.u64 %0, t; }"
        : "=r"(a) : "l"(p));
    return a;
}
__device__ __forceinline__ void cp16(uint32_t dst, const void* src) {
    asm volatile("cp.async.cg.shared.global [%0], [%1], 16;"
                 :: "r"(dst), "l"(src) : "memory");
}
__device__ __forceinline__ void cp_commit() {
    asm volatile("cp.async.commit_group;" ::: "memory");
}
template <int N>
__device__ __forceinline__ void cp_wait() {
    asm volatile("cp.async.wait_group %0;" :: "n"(N) : "memory");
}
__device__ __forceinline__ void ldsm4(uint32_t& r0, uint32_t& r1,
                                      uint32_t& r2, uint32_t& r3, uint32_t a) {
    asm volatile("ldmatrix.sync.aligned.m8n8.x4.shared.b16 {%0,%1,%2,%3}, [%4];"
                 : "=r"(r0), "=r"(r1), "=r"(r2), "=r"(r3) : "r"(a));
}
__device__ __forceinline__ void ldsm4t(uint32_t& r0, uint32_t& r1,
                                       uint32_t& r2, uint32_t& r3, uint32_t a) {
    asm volatile("ldmatrix.sync.aligned.m8n8.x4.trans.shared.b16 {%0,%1,%2,%3}, [%4];"
                 : "=r"(r0), "=r"(r1), "=r"(r2), "=r"(r3) : "r"(a));
}
__device__ __forceinline__ void mma16816(float* d, const uint32_t* a,
                                         const uint32_t* b) {
    asm volatile(
        "mma.sync.aligned.m16n8k16.row.col.f32.f16.f16.f32 "
        "{%0,%1,%2,%3}, {%4,%5,%6,%7}, {%8,%9}, {%0,%1,%2,%3};"
        : "+f"(d[0]), "+f"(d[1]), "+f"(d[2]), "+f"(d[3])
        : "r"(a[0]), "r"(a[1]), "r"(a[2]), "r"(a[3]), "r"(b[0]), "r"(b[1]));
}
// A-normal tile [128m x BKk] (BK/8 segments of 2KB). MUL=2 for BK32,
// MUL=1 for BK64. Conflict-free for cp.async stores and ldmatrix phases.
__device__ __forceinline__ uint32_t swzA(int r, int c16, int mul) {
    return (uint32_t)((c16 << 11) + ((r >> 3) << 7) + (((r + mul * c16) & 7) << 4));
}
// K-major tile [BKk x 128cols] (256B rows): XOR swizzle.
__device__ __forceinline__ uint32_t swz_kn(int r, int c) {
    return (uint32_t)(r * 256 + ((c & 8) << 4) + (((c ^ r) & 7) << 4));
}
// K-major tile [BKk x 256cols] (512B rows): XOR swizzle; 8 lanes of an
// ldmatrix phase hit 8 distinct 16B slots of one 128B line -> conflict-free.
__device__ __forceinline__ uint32_t swz_b512(int r, int c) {
    return (uint32_t)(r * 512 + ((c & 24) << 4) + (((c ^ r) & 7) << 4));
}

// ===========================================================================
// 3-term GEMM (precision-critical tr = h_r @ Wr): CTA 128x128, BK32,
// 3 stages x 32 KB, 8 warps 2Mx4N (warp 64x32), 2 CTAs/SM.
// C = (Ah+Al) @ (Bh+Bl) keeping Ah*Bh + Ah*Bl + Al*Bh.
// ===========================================================================
__device__ __forceinline__ void load_stage3(uint32_t sb,
    const __half* __restrict__ Ahi, const __half* __restrict__ Alo, int lda,
    int bm,
    const __half* __restrict__ Bhi, const __half* __restrict__ Blo, int ldb,
    int bn, int k0, int tid)
{
    #pragma unroll
    for (int i = 0; i < 2; i++) {
        const int idx = tid + i * 256;
        const int r = idx >> 4, c = idx & 15;
        const uint32_t so = swz_kn(r, c);
        const size_t bo = (size_t)(k0 + r) * ldb + bn + c * 8;
        cp16(sb + 16384 + so, Bhi + bo);
        cp16(sb + 24576 + so, Blo + bo);
        const int c16 = idx & 3, ra = idx >> 2;
        const uint32_t soA = swzA(ra, c16, 2);
        const size_t ao = (size_t)(bm + ra) * lda + k0 + c16 * 8;
        cp16(sb + soA,        Ahi + ao);
        cp16(sb + 8192 + soA, Alo + ao);
    }
}

__global__ void __launch_bounds__(256, 2)
hmma_gemm3_k(int M, int Kc,
             const __half* __restrict__ Ahi, const __half* __restrict__ Alo,
             int lda,
             const __half* __restrict__ Bhi, const __half* __restrict__ Blo,
             int ldb,
             float* __restrict__ C, int ldc)
{
    constexpr int STAGE = 32768, NST = 3;
    extern __shared__ char sm[];
    const uint32_t smb = smem_u32(sm);
    const int tid  = threadIdx.x;
    const int wid  = tid >> 5;
    const int lane = tid & 31;
    const int warp_m = wid & 1;
    const int warp_n = wid >> 1;
    const int bm = blockIdx.y * 128;
    const int bn = blockIdx.x * 128;

    float acc[4][4][4];
    #pragma unroll
    for (int mf = 0; mf < 4; mf++)
        #pragma unroll
        for (int nt = 0; nt < 4; nt++)
            #pragma unroll
            for (int i = 0; i < 4; i++) acc[mf][nt][i] = 0.f;

    #pragma unroll
    for (int s = 0; s < NST - 1; s++) {
        if (s < Kc)
            load_stage3(smb + s * STAGE, Ahi, Alo, lda, bm,
                        Bhi, Blo, ldb, bn, s * 32, tid);
        cp_commit();
    }

    const int aN_r  = warp_m * 64 + (lane & 15);
    const int aN_ch = lane >> 4;
    const int b_r   = lane & 15;
    const int b_cb  = warp_n * 4 + (lane >> 4);

    for (int ci = 0; ci < Kc; ci++) {
        cp_wait<NST - 2>();
        __syncthreads();
        if (ci + NST - 1 < Kc)
            load_stage3(smb + ((ci + NST - 1) % NST) * STAGE, Ahi, Alo, lda,
                        bm, Bhi, Blo, ldb, bn, (ci + NST - 1) * 32, tid);
        cp_commit();

        const uint32_t sb = smb + (ci % NST) * STAGE;
        #pragma unroll
        for (int ks = 0; ks < 2; ks++) {
            uint32_t ah[4][4], al[4][4], bh[2][4], bl[2][4];
            #pragma unroll
            for (int mf = 0; mf < 4; mf++) {
                const uint32_t ad = sb + swzA(aN_r + mf * 16, ks * 2 + aN_ch, 2);
                ldsm4(ah[mf][0], ah[mf][1], ah[mf][2], ah[mf][3], ad);
                ldsm4(al[mf][0], al[mf][1], al[mf][2], al[mf][3], ad + 8192);
            }
            #pragma unroll
            for (int np = 0; np < 2; np++) {
                const uint32_t bd = sb + 16384 + swz_kn(ks * 16 + b_r, b_cb + np * 2);
                ldsm4t(bh[np][0], bh[np][1], bh[np][2], bh[np][3], bd);
                ldsm4t(bl[np][0], bl[np][1], bl[np][2], bl[np][3], bd + 8192);
            }
            #pragma unroll
            for (int mf = 0; mf < 4; mf++) {
                #pragma unroll
                for (int np = 0; np < 2; np++) {
                    mma16816(acc[mf][np * 2],     ah[mf], &bh[np][0]);
                    mma16816(acc[mf][np * 2 + 1], ah[mf], &bh[np][2]);
                    mma16816(acc[mf][np * 2],     ah[mf], &bl[np][0]);
                    mma16816(acc[mf][np * 2 + 1], ah[mf], &bl[np][2]);
                    mma16816(acc[mf][np * 2],     al[mf], &bh[np][0]);
                    mma16816(acc[mf][np * 2 + 1], al[mf], &bh[np][2]);
                }
            }
        }
    }

    const int row_in = lane >> 2;
    const int col_in = (lane & 3) * 2;
    #pragma unroll
    for (int mf = 0; mf < 4; mf++) {
        #pragma unroll
        for (int h2 = 0; h2 < 2; h2++) {
            const int m = bm + warp_m * 64 + mf * 16 + row_in + h2 * 8;
            if (m >= M) continue;
            #pragma unroll
            for (int nt = 0; nt < 4; nt++) {
                const int n = bn + warp_n * 32 + nt * 8 + col_in;
                float2 o;
                o.x = acc[mf][nt][h2 * 2 + 0];
                o.y = acc[mf][nt][h2 * 2 + 1];
                *reinterpret_cast<float2*>(C + (size_t)m * ldc + n) = o;
            }
        }
    }
}
#define SMEM_3TERM (3 * 32768)

// ===========================================================================
// Wide 1-term GEMM: C[M,N] = op(A)[M,K] @ B[K,N], pure fp16 operands.
// CTA 128x256, BK64, 4 stages x 48 KB (A 16K + B 32K), 8 warps 2Mx4N
// (warp tile 64x64), 1 CTA/SM. A_TRANS=1 reads A from [K,M] row-major.
// OUT_HALF=1 writes fp16. Split-K over gridDim.z -> partials.
// ===========================================================================
#define WSTAGE 49152
#define WNST 4
#define SMEM_WIDE (WNST * WSTAGE)   // 196608 B

template <int A_TRANS>
__device__ __forceinline__ void load_stage_w(uint32_t sb,
    const __half* __restrict__ Ahi, int lda, int bm,
    const __half* __restrict__ Bhi, int ldb, int bn, int k0, int tid)
{
    // A tile: 16 KB at +0
    #pragma unroll
    for (int i = 0; i < 4; i++) {
        const int idx = tid + i * 256;
        if (A_TRANS) {
            const int r = idx >> 4, c = idx & 15;
            cp16(sb + swz_kn(r, c),
                 Ahi + (size_t)(k0 + r) * lda + bm + c * 8);
        } else {
            const int c16 = idx & 7, ra = idx >> 3;
            cp16(sb + swzA(ra, c16, 1),
                 Ahi + (size_t)(bm + ra) * lda + k0 + c16 * 8);
        }
    }
    // B tile: [64k x 256n], 32 KB at +16384
    #pragma unroll
    for (int i = 0; i < 8; i++) {
        const int idx = tid + i * 256;
        const int r = idx >> 5, c = idx & 31;
        cp16(sb + 16384 + swz_b512(r, c),
             Bhi + (size_t)(k0 + r) * ldb + bn + c * 8);
    }
}

template <int A_TRANS, int OUT_HALF>
__global__ void __launch_bounds__(256, 1)
hmma_wide_k(int M, int Kc,
            const __half* __restrict__ Ahi, int lda,
            const __half* __restrict__ Bhi, int ldb,
            void* __restrict__ Cv, int ldc, size_t part_stride)
{
    extern __shared__ char sm[];
    const uint32_t smb = smem_u32(sm);
    const int tid  = threadIdx.x;
    const int wid  = tid >> 5;
    const int lane = tid & 31;
    const int warp_m = wid & 1;    // 0..1 (64 rows each)
    const int warp_n = wid >> 1;   // 0..3 (64 cols each)
    const int bm = blockIdx.y * 128;
    const int bn = blockIdx.x * 256;

    const int P = gridDim.z, p = blockIdx.z;
    const int kbase = Kc / P, krem = Kc - kbase * P;
    const int kc0 = p * kbase + (p < krem ? p : krem);
    const int kcn = kbase + (p < krem ? 1 : 0);

    float acc[4][8][4];
    #pragma unroll
    for (int mf = 0; mf < 4; mf++)
        #pragma unroll
        for (int nt = 0; nt < 8; nt++)
            #pragma unroll
            for (int i = 0; i < 4; i++) acc[mf][nt][i] = 0.f;

    #pragma unroll
    for (int s = 0; s < WNST - 1; s++) {
        if (s < kcn)
            load_stage_w<A_TRANS>(smb + s * WSTAGE, Ahi, lda, bm,
                                  Bhi, ldb, bn, (kc0 + s) * 64, tid);
        cp_commit();
    }

    const int aN_r  = warp_m * 64 + (lane & 15);
    const int aN_ch = lane >> 4;
    const int aT_r  = (lane & 7) + ((lane >> 4) << 3);
    const int aT_cb = warp_m * 8 + ((lane >> 3) & 1);
    const int b_r   = lane & 15;
    const int b_cb  = warp_n * 8 + (lane >> 4);

    for (int ci = 0; ci < kcn; ci++) {
        cp_wait<WNST - 2>();
        __syncthreads();
        if (ci + WNST - 1 < kcn)
            load_stage_w<A_TRANS>(smb + ((ci + WNST - 1) % WNST) * WSTAGE,
                                  Ahi, lda, bm, Bhi, ldb, bn,
                                  (kc0 + ci + WNST - 1) * 64, tid);
        cp_commit();

        const uint32_t sb = smb + (ci % WNST) * WSTAGE;
        #pragma unroll
        for (int ks = 0; ks < 4; ks++) {
            uint32_t ah[4][4];
            #pragma unroll
            for (int mf = 0; mf < 4; mf++) {
                if (A_TRANS) {
                    const uint32_t ad =
                        sb + swz_kn(ks * 16 + aT_r, aT_cb + mf * 2);
                    ldsm4t(ah[mf][0], ah[mf][1], ah[mf][2], ah[mf][3], ad);
                } else {
                    const uint32_t ad =
                        sb + swzA(aN_r + mf * 16, ks * 2 + aN_ch, 1);
                    ldsm4(ah[mf][0], ah[mf][1], ah[mf][2], ah[mf][3], ad);
                }
            }
            #pragma unroll
            for (int np = 0; np < 4; np++) {
                uint32_t bh[4];
                const uint32_t bd =
                    sb + 16384 + swz_b512(ks * 16 + b_r, b_cb + np * 2);
                ldsm4t(bh[0], bh[1], bh[2], bh[3], bd);
                #pragma unroll
                for (int mf = 0; mf < 4; mf++) {
                    mma16816(acc[mf][np * 2],     ah[mf], &bh[0]);
                    mma16816(acc[mf][np * 2 + 1], ah[mf], &bh[2]);
                }
            }
        }
    }

    const int row_in = lane >> 2;
    const int col_in = (lane & 3) * 2;
    #pragma unroll
    for (int mf = 0; mf < 4; mf++) {
        #pragma unroll
        for (int h2 = 0; h2 < 2; h2++) {
            const int m = bm + warp_m * 64 + mf * 16 + row_in + h2 * 8;
            if (m >= M) continue;
            #pragma unroll
            for (int nt = 0; nt < 8; nt++) {
                const int n = bn + warp_n * 64 + nt * 8 + col_in;
                const float v0 = acc[mf][nt][h2 * 2 + 0];
                const float v1 = acc[mf][nt][h2 * 2 + 1];
                if (OUT_HALF) {
                    __half* C = (__half*)Cv + part_stride * (size_t)p;
                    *reinterpret_cast<__half2*>(C + (size_t)m * ldc + n) =
                        __halves2half2(__float2half_rn(v0), __float2half_rn(v1));
                } else {
                    float* C = (float*)Cv + part_stride * (size_t)p;
                    float2 o; o.x = v0; o.y = v1;
                    *reinterpret_cast<float2*>(C + (size_t)m * ldc + n) = o;
                }
            }
        }
    }
}

// ---------------------------------------------------------------------------
// reduce + epilogue: v = relu(invdeg[m] * sum_p part[p] + add[m,n])
//   MODE 0: fp32 out (rows < M). MODE 1: fp16 hi+lo. MODE 2: fp16 hi only.
// ---------------------------------------------------------------------------
template <int MODE>
__global__ void reduce_epi_k(int M, int MP, int P,
                             const float* __restrict__ part, size_t pstride,
                             const float* __restrict__ invdeg,
                             const float* __restrict__ add, int ld_add,
                             float* __restrict__ out32,
                             __half* __restrict__ hi, __half* __restrict__ lo)
{
    int idx = blockIdx.x * 256 + threadIdx.x;   // over MP * 128 float4s
    if (idx >= MP * 128) return;
    int m = idx >> 7, q = (idx & 127) << 2;
    float4 o = make_float4(0.f, 0.f, 0.f, 0.f);
    if (m < M) {
        float4 s = make_float4(0.f, 0.f, 0.f, 0.f);
        for (int pp = 0; pp < P; pp++) {
            const float4 v = *reinterpret_cast<const float4*>(
                part + pp * pstride + (size_t)m * DD + q);
            s.x += v.x; s.y += v.y; s.z += v.z; s.w += v.w;
        }
        const float sc = invdeg[m];
        const float4 a = *reinterpret_cast<const float4*>(
            add + (size_t)m * ld_add + q);
        o.x = fmaxf(fmaf(sc, s.x, a.x), 0.f);
        o.y = fmaxf(fmaf(sc, s.y, a.y), 0.f);
        o.z = fmaxf(fmaf(sc, s.z, a.z), 0.f);
        o.w = fmaxf(fmaf(sc, s.w, a.w), 0.f);
    }
    if (MODE == 0) {
        if (m < M)
            *reinterpret_cast<float4*>(out32 + (size_t)m * DD + q) = o;
    } else {
        __half h0 = __float2half_rn(o.x), h1 = __float2half_rn(o.y);
        __half h2 = __float2half_rn(o.z), h3 = __float2half_rn(o.w);
        const size_t off = (size_t)m * DD + q;
        *reinterpret_cast<__half2*>(hi + off)     = __halves2half2(h0, h1);
        *reinterpret_cast<__half2*>(hi + off + 2) = __halves2half2(h2, h3);
        if (MODE == 1) {
            *reinterpret_cast<__half2*>(lo + off) = __halves2half2(
                __float2half_rn(o.x - __half2float(h0)),
                __float2half_rn(o.y - __half2float(h1)));
            *reinterpret_cast<__half2*>(lo + off + 2) = __halves2half2(
                __float2half_rn(o.z - __half2float(h2)),
                __float2half_rn(o.w - __half2float(h3)));
        }
    }
}

// ---------------------------------------------------------------------------
// Conversions
// ---------------------------------------------------------------------------
__global__ void splitA_hi_k(const float* __restrict__ A,
                            __half* __restrict__ hi,
                            float* __restrict__ invdeg)
{
    const int r = blockIdx.x;           // 0..NR_P-1
    const bool real = (r < NR);
    const int tid = threadIdx.x;        // 256
    float acc = 0.f;
    for (int c4 = tid; c4 < NS_P / 4; c4 += 256) {
        float4 v = make_float4(0.f, 0.f, 0.f, 0.f);
        if (real && c4 < NS / 4)
            v = *reinterpret_cast<const float4*>(A + (size_t)r * NS + c4 * 4);
        acc += (v.x + v.y) + (v.z + v.w);
        const size_t o = (size_t)r * NS_P + c4 * 4;
        *reinterpret_cast<__half2*>(hi + o) =
            __halves2half2(__float2half_rn(v.x), __float2half_rn(v.y));
        *reinterpret_cast<__half2*>(hi + o + 2) =
            __halves2half2(__float2half_rn(v.z), __float2half_rn(v.w));
    }
    #pragma unroll
    for (int off = 16; off; off >>= 1) acc += __shfl_down_sync(0xffffffffu, acc, off);
    __shared__ float ws[8];
    if ((tid & 31) == 0) ws[tid >> 5] = acc;
    __syncthreads();
    if (tid == 0 && real) {
        float s = 0.f;
        #pragma unroll
        for (int w = 0; w < 8; w++) s += ws[w];
        invdeg[r] = 1.f / (s + 1e-6f);
    }
}

__global__ void split_cols_k(const float* __restrict__ in, int ld, int col0,
                             __half* __restrict__ hi, __half* __restrict__ lo,
                             int M)
{
    const int r = blockIdx.x;
    const int c = threadIdx.x * 4;
    float4 v = make_float4(0.f, 0.f, 0.f, 0.f);
    if (r < M)
        v = *reinterpret_cast<const float4*>(in + (size_t)r * ld + col0 + c);
    __half h0 = __float2half_rn(v.x), h1 = __float2half_rn(v.y);
    __half h2 = __float2half_rn(v.z), h3 = __float2half_rn(v.w);
    const size_t o = (size_t)r * DD + c;
    *reinterpret_cast<__half2*>(hi + o)     = __halves2half2(h0, h1);
    *reinterpret_cast<__half2*>(hi + o + 2) = __halves2half2(h2, h3);
    *reinterpret_cast<__half2*>(lo + o) = __halves2half2(
        __float2half_rn(v.x - __half2float(h0)),
        __float2half_rn(v.y - __half2float(h1)));
    *reinterpret_cast<__half2*>(lo + o + 2) = __halves2half2(
        __float2half_rn(v.z - __half2float(h2)),
        __float2half_rn(v.w - __half2float(h3)));
}

__global__ void split_cols_hi_k(const float* __restrict__ in, int ld, int col0,
                                __half* __restrict__ hi, int M)
{
    const int r = blockIdx.x;
    const int c = threadIdx.x * 4;
    float4 v = make_float4(0.f, 0.f, 0.f, 0.f);
    if (r < M)
        v = *reinterpret_cast<const float4*>(in + (size_t)r * ld + col0 + c);
    const size_t o = (size_t)r * DD + c;
    *reinterpret_cast<__half2*>(hi + o) =
        __halves2half2(__float2half_rn(v.x), __float2half_rn(v.y));
    *reinterpret_cast<__half2*>(hi + o + 2) =
        __halves2half2(__float2half_rn(v.z), __float2half_rn(v.w));
}

__global__ void splitW_hi_k(const float* __restrict__ W,
                            const float* __restrict__ V,
                            __half* __restrict__ hi)
{
    const int row = blockIdx.x;           // 0 .. NL*512-1
    const int l = row >> 9, k = row & 511;
    const int n = threadIdx.x * 4;        // 256 threads -> 1024 cols
    const float* src = (n < 512) ? (W + ((size_t)l * DD + k) * DD + n)
                                 : (V + ((size_t)l * DD + k) * DD + n - 512);
    float4 v = *reinterpret_cast<const float4*>(src);
    const size_t o = (size_t)row * 1024 + n;
    *reinterpret_cast<__half2*>(hi + o) =
        __halves2half2(__float2half_rn(v.x), __float2half_rn(v.y));
    *reinterpret_cast<__half2*>(hi + o + 2) =
        __halves2half2(__float2half_rn(v.z), __float2half_rn(v.w));
}

// ---------------------------------------------------------------------------
// Column degrees
// ---------------------------------------------------------------------------
__global__ void colsum_part_k(const float* __restrict__ A, float* __restrict__ part)
{
    int s = blockIdx.x * blockDim.x + threadIdx.x;
    if (s >= NS) return;
    int chunk = blockIdx.y;
    const int rows = NR / COL_CHUNKS;
    const float* p = A + (size_t)(chunk * rows) * NS + s;
    float acc = 0.f;
    for (int r = 0; r < rows; r++) acc += p[(size_t)r * NS];
    part[chunk * NS + s] = acc;
}
__global__ void colsum_fin_k(const float* __restrict__ part, float* __restrict__ invdeg)
{
    int s = blockIdx.x * blockDim.x + threadIdx.x;
    if (s >= NS) return;
    float acc = 0.f;
    #pragma unroll
    for (int c = 0; c < COL_CHUNKS; c++) acc += part[c * NS + s];
    invdeg[s] = 1.f / (acc + 1e-6f);
}

// ---------------------------------------------------------------------------
// Host orchestration
// ---------------------------------------------------------------------------
extern "C" void kernel_launch(void* const* d_in, const int* in_sizes, int n_in,
                              void* d_out, int out_size)
{
    const float* h_s_in = (const float*)d_in[0];  // [NS, DD]
    const float* A      = (const float*)d_in[1];  // [NR, NS]
    const float* r_emb  = (const float*)d_in[2];  // [NR, DD]
    const float* Wr     = (const float*)d_in[3];  // [NL, DD, DD]
    const float* Ws     = (const float*)d_in[4];
    const float* Vr     = (const float*)d_in[5];
    const float* Vs     = (const float*)d_in[6];
    float* out = (float*)d_out;                   // [NR, DD]

    cudaFuncSetAttribute((const void*)hmma_gemm3_k,
                         cudaFuncAttributeMaxDynamicSharedMemorySize, SMEM_3TERM);
    cudaFuncSetAttribute((const void*)hmma_wide_k<0, 0>,
                         cudaFuncAttributeMaxDynamicSharedMemorySize, SMEM_WIDE);
    cudaFuncSetAttribute((const void*)hmma_wide_k<0, 1>,
                         cudaFuncAttributeMaxDynamicSharedMemorySize, SMEM_WIDE);
    cudaFuncSetAttribute((const void*)hmma_wide_k<1, 0>,
                         cudaFuncAttributeMaxDynamicSharedMemorySize, SMEM_WIDE);

    float *invdr, *invds, *colpart, *fS, *tr, *partR, *partS;
    __half *Ahi, *hrhi, *hrlo, *hshi, *gshi, *grhi, *WShi, *Wrhi, *Wrlo, *Vrhi;
    cudaGetSymbolAddress((void**)&invdr,   g_invdeg_r);
    cudaGetSymbolAddress((void**)&invds,   g_invdeg_s);
    cudaGetSymbolAddress((void**)&colpart, g_colpart);
    cudaGetSymbolAddress((void**)&fS,    g_fS);
    cudaGetSymbolAddress((void**)&tr,    g_tr);
    cudaGetSymbolAddress((void**)&partR, g_partR);
    cudaGetSymbolAddress((void**)&partS, g_partS);
    cudaGetSymbolAddress((void**)&Ahi,  g_Ahi);
    cudaGetSymbolAddress((void**)&hrhi, g_hrhi);
    cudaGetSymbolAddress((void**)&hrlo, g_hrlo);
    cudaGetSymbolAddress((void**)&hshi, g_hshi);
    cudaGetSymbolAddress((void**)&gshi, g_gshi);
    cudaGetSymbolAddress((void**)&grhi, g_grhi);
    cudaGetSymbolAddress((void**)&WShi, g_WShi);
    cudaGetSymbolAddress((void**)&Wrhi, g_Wrhi);
    cudaGetSymbolAddress((void**)&Wrlo, g_Wrlo);
    cudaGetSymbolAddress((void**)&Vrhi, g_Vrhi);

    // 1: h_s hi split  2: [Ws|Vs] hi  3: Wr hi/lo  4: fS GEMM (profiled)
    split_cols_hi_k<<<NS_P, 128>>>(h_s_in, DD, 0, hshi, NS);
    splitW_hi_k<<<NL * DD, 256>>>(Ws, Vs, WShi);
    split_cols_k<<<NL * DD, 128>>>(Wr, DD, 0, Wrhi, Wrlo, NL * DD);

    for (int l = 0; l < NL; l++) {
        const bool last = (l == NL - 1);
        const int NW = last ? 512 : 1024;

        // fS = h_s @ [Ws|Vs][l] -> fp32 [NS, 1024]   (1-term wide)
        hmma_wide_k<0, 0><<<dim3(NW / 256, NS_P / 128, 1), 256, SMEM_WIDE>>>(
            NS, DD / 64, hshi, DD,
            WShi + (size_t)l * DD * 1024, 1024, fS, 1024, 0);

        if (l == 0) {
            split_cols_hi_k<<<NL * DD, 128>>>(Vr, DD, 0, Vrhi, NL * DD);
            split_cols_k<<<NR_P, 128>>>(r_emb, DD, 0, hrhi, hrlo, NR);
            splitA_hi_k<<<NR_P, 256>>>(A, Ahi, invdr);
            colsum_part_k<<<dim3((NS + 255) / 256, COL_CHUNKS), 256>>>(A, colpart);
            colsum_fin_k<<<(NS + 255) / 256, 256>>>(colpart, invds);
        }

        // tr = h_r @ Wr[l] -> fp32 [NR, 512]   (3-term, precision-critical)
        hmma_gemm3_k<<<dim3(4, NR_P / 128, 1), 256, SMEM_3TERM>>>(
            NR, DD / 32, hrhi, hrlo, DD,
            Wrhi + (size_t)l * DD * DD, Wrlo + (size_t)l * DD * DD, DD,
            tr, DD);

        // gs -> fp16 hi (aggregation operand)
        split_cols_hi_k<<<NS_P, 128>>>(fS, 1024, 0, gshi, NS);

        // big: partR = A @ gs (1-term wide, split-K)
        hmma_wide_k<0, 0><<<dim3(2, NR_P / 128, KSPLIT_R), 256, SMEM_WIDE>>>(
            NR, NS_P / 64, Ahi, NS_P, gshi, DD,
            partR, DD, (size_t)NR * DD);

        if (!last) {
            // gr = h_r @ Vr[l] -> fp16 direct (uses OLD h_r; before reduceR)
            hmma_wide_k<0, 1><<<dim3(2, NR_P / 128, 1), 256, SMEM_WIDE>>>(
                NR_P, DD / 64, hrhi, DD,
                Vrhi + (size_t)l * DD * DD, DD, grhi, DD, 0);
        }

        // h_r' = relu(invdeg_r * (A @ gs) + tr)
        if (last) {
            reduce_epi_k<0><<<(NR * 128 + 255) / 256, 256>>>(
                NR, NR, KSPLIT_R, partR, (size_t)NR * DD, invdr, tr, DD,
                out, nullptr, nullptr);
        } else {
            reduce_epi_k<1><<<(NR_P * 128 + 255) / 256, 256>>>(
                NR, NR_P, KSPLIT_R, partR, (size_t)NR * DD, invdr, tr, DD,
                nullptr, hrhi, hrlo);

            // big: partS = A^T @ gr (1-term wide, A read transposed)
            hmma_wide_k<1, 0><<<dim3(2, NS_P / 128, KSPLIT_S), 256, SMEM_WIDE>>>(
                NS, KR_P / 64, Ahi, NS_P, grhi, DD,
                partS, DD, (size_t)NS * DD);

            // h_s' = relu(invdeg_s * (A^T @ gr) + ts), hi-only
            reduce_epi_k<2><<<(NS_P * 128 + 255) / 256, 256>>>(
                NS, NS_P, KSPLIT_S, partS, (size_t)NS * DD, invds, fS + 512, 1024,
                nullptr, hshi, nullptr);
        }
    }
}

// round 14
// speedup vs baseline: 1.0051x; 1.0051x over previous
#include <cuda_runtime.h>
#include <cuda_fp16.h>
#include <cstdint>

// ---------------------------------------------------------------------------
// Problem constants
// ---------------------------------------------------------------------------
#define NR 20000          // readings
#define NS 5000           // skills
#define DD 512            // embedding dim
#define NL 3              // layers
#define NR_P 20096        // NR padded to 128 (314 tiles of 64)
#define NS_P 5120         // NS padded to 128 (80 tiles of 64)
#define KR_P 20032        // NR padded to 64 (K dim of A^T GEMM, 313 chunks)
#define COL_CHUNKS 16
#define KSPLIT_S 4        // split-K for A^T@gr (grid 4*80*4 = 1280)

// ---------------------------------------------------------------------------
// Device scratch (no cudaMalloc allowed)
// ---------------------------------------------------------------------------
__device__ float g_invdeg_r[NR];
__device__ float g_invdeg_s[NS];
__device__ float g_colpart[COL_CHUNKS * NS];

__device__ __align__(16) __half g_Ahi[(size_t)NR_P * NS_P];
__device__ __align__(16) __half g_hrhi[(size_t)NR_P * DD];
__device__ __align__(16) __half g_hrlo[(size_t)NR_P * DD];
__device__ __align__(16) __half g_hshi[(size_t)NS_P * DD];
__device__ __align__(16) __half g_gshi[(size_t)NS_P * DD];
__device__ __align__(16) __half g_grhi[(size_t)NR_P * DD];
__device__ __align__(16) __half g_WShi[(size_t)NL * DD * 1024];  // [Ws|Vs] hi
__device__ __align__(16) __half g_Wrhi[(size_t)NL * DD * DD];
__device__ __align__(16) __half g_Wrlo[(size_t)NL * DD * DD];
__device__ __align__(16) __half g_Vrhi[(size_t)NL * DD * DD];

__device__ float g_fS[(size_t)NS * 1024];            // [gs | ts]
__device__ float g_tr[(size_t)NR * DD];
__device__ float g_partS[(size_t)KSPLIT_S * NS * DD];

// ---------------------------------------------------------------------------
// PTX helpers (Ampere-era ISA: compiles for plain compute_103 target)
// ---------------------------------------------------------------------------
__device__ __forceinline__ uint32_t smem_u32(const void* p) {
    uint32_t a;
    asm("{ .reg .u64 t; cvta.to.shared.u64 t, %1; cvt.u32.u64 %0, t; }"
        : "=r"(a) : "l"(p));
    return a;
}
__device__ __forceinline__ void cp16(uint32_t dst, const void* src) {
    asm volatile("cp.async.cg.shared.global [%0], [%1], 16;"
                 :: "r"(dst), "l"(src) : "memory");
}
__device__ __forceinline__ void cp_commit() {
    asm volatile("cp.async.commit_group;" ::: "memory");
}
template <int N>
__device__ __forceinline__ void cp_wait() {
    asm volatile("cp.async.wait_group %0;" :: "n"(N) : "memory");
}
__device__ __forceinline__ void ldsm4(uint32_t& r0, uint32_t& r1,
                                      uint32_t& r2, uint32_t& r3, uint32_t a) {
    asm volatile("ldmatrix.sync.aligned.m8n8.x4.shared.b16 {%0,%1,%2,%3}, [%4];"
                 : "=r"(r0), "=r"(r1), "=r"(r2), "=r"(r3) : "r"(a));
}
__device__ __forceinline__ void ldsm4t(uint32_t& r0, uint32_t& r1,
                                       uint32_t& r2, uint32_t& r3, uint32_t a) {
    asm volatile("ldmatrix.sync.aligned.m8n8.x4.trans.shared.b16 {%0,%1,%2,%3}, [%4];"
                 : "=r"(r0), "=r"(r1), "=r"(r2), "=r"(r3) : "r"(a));
}
__device__ __forceinline__ void mma16816(float* d, const uint32_t* a,
                                         const uint32_t* b) {
    asm volatile(
        "mma.sync.aligned.m16n8k16.row.col.f32.f16.f16.f32 "
        "{%0,%1,%2,%3}, {%4,%5,%6,%7}, {%8,%9}, {%0,%1,%2,%3};"
        : "+f"(d[0]), "+f"(d[1]), "+f"(d[2]), "+f"(d[3])
        : "r"(a[0]), "r"(a[1]), "r"(a[2]), "r"(a[3]), "r"(b[0]), "r"(b[1]));
}
// 128-row A tile [128m x 32k], 2KB segments per 16B k-chunk (3-term kernel).
__device__ __forceinline__ uint32_t swzA128(int r, int c16) {
    return (uint32_t)((c16 << 11) + ((r >> 3) << 7) + (((r + 2 * c16) & 7) << 4));
}
// 64-row A tile [64m x 64k], 1KB segments per 16B k-chunk (tall kernel).
__device__ __forceinline__ uint32_t swzA64(int r, int c16) {
    return (uint32_t)((c16 << 10) + ((r >> 3) << 7) + (((r + c16) & 7) << 4));
}
// K-major tile [k x 128cols] (256B rows): XOR swizzle.
__device__ __forceinline__ uint32_t swz_kn(int r, int c) {
    return (uint32_t)(r * 256 + ((c & 8) << 4) + (((c ^ r) & 7) << 4));
}
// K-major tile [k x 64cols] (128B rows): XOR swizzle (tall A^T tile).
__device__ __forceinline__ uint32_t swz_k64(int r, int c) {
    return (uint32_t)(r * 128 + (((c ^ r) & 7) << 4));
}

// ===========================================================================
// 3-term GEMM (precision-critical tr = h_r @ Wr): CTA 128x128, BK32,
// 3 stages x 32 KB, 8 warps 2Mx4N (warp 64x32), 2 CTAs/SM.  (proven R12)
// ===========================================================================
__device__ __forceinline__ void load_stage3(uint32_t sb,
    const __half* __restrict__ Ahi, const __half* __restrict__ Alo, int lda,
    int bm,
    const __half* __restrict__ Bhi, const __half* __restrict__ Blo, int ldb,
    int bn, int k0, int tid)
{
    #pragma unroll
    for (int i = 0; i < 2; i++) {
        const int idx = tid + i * 256;
        const int r = idx >> 4, c = idx & 15;
        const uint32_t so = swz_kn(r, c);
        const size_t bo = (size_t)(k0 + r) * ldb + bn + c * 8;
        cp16(sb + 16384 + so, Bhi + bo);
        cp16(sb + 24576 + so, Blo + bo);
        const int c16 = idx & 3, ra = idx >> 2;
        const uint32_t soA = swzA128(ra, c16);
        const size_t ao = (size_t)(bm + ra) * lda + k0 + c16 * 8;
        cp16(sb + soA,        Ahi + ao);
        cp16(sb + 8192 + soA, Alo + ao);
    }
}

__global__ void __launch_bounds__(256, 2)
hmma_gemm3_k(int M, int Kc,
             const __half* __restrict__ Ahi, const __half* __restrict__ Alo,
             int lda,
             const __half* __restrict__ Bhi, const __half* __restrict__ Blo,
             int ldb,
             float* __restrict__ C, int ldc)
{
    constexpr int STAGE = 32768, NST = 3;
    extern __shared__ char sm[];
    const uint32_t smb = smem_u32(sm);
    const int tid  = threadIdx.x;
    const int wid  = tid >> 5;
    const int lane = tid & 31;
    const int warp_m = wid & 1;
    const int warp_n = wid >> 1;
    const int bm = blockIdx.y * 128;
    const int bn = blockIdx.x * 128;

    float acc[4][4][4];
    #pragma unroll
    for (int mf = 0; mf < 4; mf++)
        #pragma unroll
        for (int nt = 0; nt < 4; nt++)
            #pragma unroll
            for (int i = 0; i < 4; i++) acc[mf][nt][i] = 0.f;

    #pragma unroll
    for (int s = 0; s < NST - 1; s++) {
        if (s < Kc)
            load_stage3(smb + s * STAGE, Ahi, Alo, lda, bm,
                        Bhi, Blo, ldb, bn, s * 32, tid);
        cp_commit();
    }

    const int aN_r  = warp_m * 64 + (lane & 15);
    const int aN_ch = lane >> 4;
    const int b_r   = lane & 15;
    const int b_cb  = warp_n * 4 + (lane >> 4);

    for (int ci = 0; ci < Kc; ci++) {
        cp_wait<NST - 2>();
        __syncthreads();
        if (ci + NST - 1 < Kc)
            load_stage3(smb + ((ci + NST - 1) % NST) * STAGE, Ahi, Alo, lda,
                        bm, Bhi, Blo, ldb, bn, (ci + NST - 1) * 32, tid);
        cp_commit();

        const uint32_t sb = smb + (ci % NST) * STAGE;
        #pragma unroll
        for (int ks = 0; ks < 2; ks++) {
            uint32_t ah[4][4], al[4][4], bh[2][4], bl[2][4];
            #pragma unroll
            for (int mf = 0; mf < 4; mf++) {
                const uint32_t ad = sb + swzA128(aN_r + mf * 16, ks * 2 + aN_ch);
                ldsm4(ah[mf][0], ah[mf][1], ah[mf][2], ah[mf][3], ad);
                ldsm4(al[mf][0], al[mf][1], al[mf][2], al[mf][3], ad + 8192);
            }
            #pragma unroll
            for (int np = 0; np < 2; np++) {
                const uint32_t bd = sb + 16384 + swz_kn(ks * 16 + b_r, b_cb + np * 2);
                ldsm4t(bh[np][0], bh[np][1], bh[np][2], bh[np][3], bd);
                ldsm4t(bl[np][0], bl[np][1], bl[np][2], bl[np][3], bd + 8192);
            }
            #pragma unroll
            for (int mf = 0; mf < 4; mf++) {
                #pragma unroll
                for (int np = 0; np < 2; np++) {
                    mma16816(acc[mf][np * 2],     ah[mf], &bh[np][0]);
                    mma16816(acc[mf][np * 2 + 1], ah[mf], &bh[np][2]);
                    mma16816(acc[mf][np * 2],     ah[mf], &bl[np][0]);
                    mma16816(acc[mf][np * 2 + 1], ah[mf], &bl[np][2]);
                    mma16816(acc[mf][np * 2],     al[mf], &bh[np][0]);
                    mma16816(acc[mf][np * 2 + 1], al[mf], &bh[np][2]);
                }
            }
        }
    }

    const int row_in = lane >> 2;
    const int col_in = (lane & 3) * 2;
    #pragma unroll
    for (int mf = 0; mf < 4; mf++) {
        #pragma unroll
        for (int h2 = 0; h2 < 2; h2++) {
            const int m = bm + warp_m * 64 + mf * 16 + row_in + h2 * 8;
            if (m >= M) continue;
            #pragma unroll
            for (int nt = 0; nt < 4; nt++) {
                const int n = bn + warp_n * 32 + nt * 8 + col_in;
                float2 o;
                o.x = acc[mf][nt][h2 * 2 + 0];
                o.y = acc[mf][nt][h2 * 2 + 1];
                *reinterpret_cast<float2*>(C + (size_t)m * ldc + n) = o;
            }
        }
    }
}
#define SMEM_3TERM (3 * 32768)

// ===========================================================================
// Tall 1-term GEMM: C[M,N] = op(A)[M,K] @ B[K,N], pure fp16 operands.
// CTA 64x128, BK64, 4 stages x 24 KB (A 8K + B 16K), 8 warps 2Mx4N
// (warp tile 32x32), 2 CTAs/SM. A_TRANS=1 reads A from [K,M] row-major.
// MODE 0: raw fp32 (+ split-K partials via gridDim.z)
// MODE 1: raw fp16
// MODE 2: fused epi fp32:   relu(rowscale[m]*acc + add[m,n])
// MODE 3: fused epi fp16 hi+lo (padded rows m>=M get zeros)
// ===========================================================================
#define TSTAGE 24576
#define TNST 4
#define SMEM_TALL (TNST * TSTAGE)   // 98304 B

template <int A_TRANS>
__device__ __forceinline__ void load_stage_t(uint32_t sb,
    const __half* __restrict__ Ahi, int lda, int bm,
    const __half* __restrict__ Bhi, int ldb, int bn, int k0, int tid)
{
    // A tile: 8 KB at +0
    #pragma unroll
    for (int i = 0; i < 2; i++) {
        const int idx = tid + i * 256;
        if (A_TRANS) {
            const int r = idx >> 3, c = idx & 7;     // r: 0..63 k, c: m chunk
            cp16(sb + swz_k64(r, c),
                 Ahi + (size_t)(k0 + r) * lda + bm + c * 8);
        } else {
            const int c16 = idx & 7, ra = idx >> 3;  // ra: 0..63 m
            cp16(sb + swzA64(ra, c16),
                 Ahi + (size_t)(bm + ra) * lda + k0 + c16 * 8);
        }
    }
    // B tile: [64k x 128n], 16 KB at +8192
    #pragma unroll
    for (int i = 0; i < 4; i++) {
        const int idx = tid + i * 256;
        const int r = idx >> 4, c = idx & 15;
        cp16(sb + 8192 + swz_kn(r, c),
             Bhi + (size_t)(k0 + r) * ldb + bn + c * 8);
    }
}

template <int A_TRANS, int MODE>
__global__ void __launch_bounds__(256, 2)
hmma_tall_k(int M, int Kc,
            const __half* __restrict__ Ahi, int lda,
            const __half* __restrict__ Bhi, int ldb,
            void* __restrict__ Cv, int ldc, size_t part_stride,
            const float* __restrict__ rowscale,
            const float* __restrict__ addend, int ld_add,
            __half* __restrict__ lo_out)
{
    extern __shared__ char sm[];
    const uint32_t smb = smem_u32(sm);
    const int tid  = threadIdx.x;
    const int wid  = tid >> 5;
    const int lane = tid & 31;
    const int warp_m = wid & 1;    // 0..1 (32 rows each)
    const int warp_n = wid >> 1;   // 0..3 (32 cols each)
    const int bm = blockIdx.y * 64;
    const int bn = blockIdx.x * 128;

    const int P = gridDim.z, p = blockIdx.z;
    const int kbase = Kc / P, krem = Kc - kbase * P;
    const int kc0 = p * kbase + (p < krem ? p : krem);
    const int kcn = kbase + (p < krem ? 1 : 0);

    float acc[2][4][4];
    #pragma unroll
    for (int mf = 0; mf < 2; mf++)
        #pragma unroll
        for (int nt = 0; nt < 4; nt++)
            #pragma unroll
            for (int i = 0; i < 4; i++) acc[mf][nt][i] = 0.f;

    #pragma unroll
    for (int s = 0; s < TNST - 1; s++) {
        if (s < kcn)
            load_stage_t<A_TRANS>(smb + s * TSTAGE, Ahi, lda, bm,
                                  Bhi, ldb, bn, (kc0 + s) * 64, tid);
        cp_commit();
    }

    const int aN_r  = warp_m * 32 + (lane & 15);        // A normal: m row
    const int aN_ch = lane >> 4;                         // A normal: 16B chunk
    const int aT_r  = (lane & 7) + ((lane >> 4) << 3);   // A trans: k row off
    const int aT_cb = warp_m * 4 + ((lane >> 3) & 1);    // A trans: m chunk
    const int b_r   = lane & 15;                         // B: k row offset
    const int b_cb  = warp_n * 4 + (lane >> 4);          // B: n chunk base

    for (int ci = 0; ci < kcn; ci++) {
        cp_wait<TNST - 2>();
        __syncthreads();
        if (ci + TNST - 1 < kcn)
            load_stage_t<A_TRANS>(smb + ((ci + TNST - 1) % TNST) * TSTAGE,
                                  Ahi, lda, bm, Bhi, ldb, bn,
                                  (kc0 + ci + TNST - 1) * 64, tid);
        cp_commit();

        const uint32_t sb = smb + (ci % TNST) * TSTAGE;
        #pragma unroll
        for (int ks = 0; ks < 4; ks++) {
            uint32_t ah[2][4], bh[2][4];
            #pragma unroll
            for (int mf = 0; mf < 2; mf++) {
                if (A_TRANS) {
                    const uint32_t ad =
                        sb + swz_k64(ks * 16 + aT_r, aT_cb + mf * 2);
                    ldsm4t(ah[mf][0], ah[mf][1], ah[mf][2], ah[mf][3], ad);
                } else {
                    const uint32_t ad =
                        sb + swzA64(aN_r + mf * 16, ks * 2 + aN_ch);
                    ldsm4(ah[mf][0], ah[mf][1], ah[mf][2], ah[mf][3], ad);
                }
            }
            #pragma unroll
            for (int np = 0; np < 2; np++) {
                const uint32_t bd =
                    sb + 8192 + swz_kn(ks * 16 + b_r, b_cb + np * 2);
                ldsm4t(bh[np][0], bh[np][1], bh[np][2], bh[np][3], bd);
            }
            #pragma unroll
            for (int mf = 0; mf < 2; mf++) {
                #pragma unroll
                for (int np = 0; np < 2; np++) {
                    mma16816(acc[mf][np * 2],     ah[mf], &bh[np][0]);
                    mma16816(acc[mf][np * 2 + 1], ah[mf], &bh[np][2]);
                }
            }
        }
    }

    const int row_in = lane >> 2;
    const int col_in = (lane & 3) * 2;
    #pragma unroll
    for (int mf = 0; mf < 2; mf++) {
        #pragma unroll
        for (int h2 = 0; h2 < 2; h2++) {
            const int m = bm + warp_m * 32 + mf * 16 + row_in + h2 * 8;
            if (MODE != 3 && m >= M) continue;
            float sc = 0.f;
            if ((MODE == 2 || MODE == 3) && m < M) sc = rowscale[m];
            #pragma unroll
            for (int nt = 0; nt < 4; nt++) {
                const int n = bn + warp_n * 32 + nt * 8 + col_in;
                float v0 = acc[mf][nt][h2 * 2 + 0];
                float v1 = acc[mf][nt][h2 * 2 + 1];
                if (MODE == 0) {
                    float* C = (float*)Cv + part_stride * (size_t)p;
                    float2 o; o.x = v0; o.y = v1;
                    *reinterpret_cast<float2*>(C + (size_t)m * ldc + n) = o;
                } else if (MODE == 1) {
                    __half* C = (__half*)Cv;
                    *reinterpret_cast<__half2*>(C + (size_t)m * ldc + n) =
                        __halves2half2(__float2half_rn(v0), __float2half_rn(v1));
                } else {
                    float o0 = 0.f, o1 = 0.f;
                    if (m < M) {
                        const float2 ad = *reinterpret_cast<const float2*>(
                            addend + (size_t)m * ld_add + n);
                        o0 = fmaxf(fmaf(sc, v0, ad.x), 0.f);
                        o1 = fmaxf(fmaf(sc, v1, ad.y), 0.f);
                    }
                    if (MODE == 2) {
                        float* C = (float*)Cv;
                        float2 o; o.x = o0; o.y = o1;
                        *reinterpret_cast<float2*>(C + (size_t)m * ldc + n) = o;
                    } else {  // MODE 3: fp16 hi + lo
                        __half h0 = __float2half_rn(o0);
                        __half h1 = __float2half_rn(o1);
                        __half* C = (__half*)Cv;
                        *reinterpret_cast<__half2*>(C + (size_t)m * ldc + n) =
                            __halves2half2(h0, h1);
                        *reinterpret_cast<__half2*>(lo_out + (size_t)m * ldc + n) =
                            __halves2half2(
                                __float2half_rn(o0 - __half2float(h0)),
                                __float2half_rn(o1 - __half2float(h1)));
                    }
                }
            }
        }
    }
}

// ---------------------------------------------------------------------------
// reduce + epilogue (bigS only): fp16 hi out, padded rows zero
// ---------------------------------------------------------------------------
__global__ void reduce_epi_hi_k(int M, int MP, int P,
                                const float* __restrict__ part, size_t pstride,
                                const float* __restrict__ invdeg,
                                const float* __restrict__ add, int ld_add,
                                __half* __restrict__ hi)
{
    int idx = blockIdx.x * 256 + threadIdx.x;   // over MP * 128 float4s
    if (idx >= MP * 128) return;
    int m = idx >> 7, q = (idx & 127) << 2;
    float4 o = make_float4(0.f, 0.f, 0.f, 0.f);
    if (m < M) {
        float4 s = make_float4(0.f, 0.f, 0.f, 0.f);
        for (int pp = 0; pp < P; pp++) {
            const float4 v = *reinterpret_cast<const float4*>(
                part + pp * pstride + (size_t)m * DD + q);
            s.x += v.x; s.y += v.y; s.z += v.z; s.w += v.w;
        }
        const float sc = invdeg[m];
        const float4 a = *reinterpret_cast<const float4*>(
            add + (size_t)m * ld_add + q);
        o.x = fmaxf(fmaf(sc, s.x, a.x), 0.f);
        o.y = fmaxf(fmaf(sc, s.y, a.y), 0.f);
        o.z = fmaxf(fmaf(sc, s.z, a.z), 0.f);
        o.w = fmaxf(fmaf(sc, s.w, a.w), 0.f);
    }
    const size_t off = (size_t)m * DD + q;
    *reinterpret_cast<__half2*>(hi + off) =
        __halves2half2(__float2half_rn(o.x), __float2half_rn(o.y));
    *reinterpret_cast<__half2*>(hi + off + 2) =
        __halves2half2(__float2half_rn(o.z), __float2half_rn(o.w));
}

// ---------------------------------------------------------------------------
// Conversions
// ---------------------------------------------------------------------------
__global__ void splitA_hi_k(const float* __restrict__ A,
                            __half* __restrict__ hi,
                            float* __restrict__ invdeg)
{
    const int r = blockIdx.x;           // 0..NR_P-1
    const bool real = (r < NR);
    const int tid = threadIdx.x;        // 256
    float acc = 0.f;
    for (int c4 = tid; c4 < NS_P / 4; c4 += 256) {
        float4 v = make_float4(0.f, 0.f, 0.f, 0.f);
        if (real && c4 < NS / 4)
            v = *reinterpret_cast<const float4*>(A + (size_t)r * NS + c4 * 4);
        acc += (v.x + v.y) + (v.z + v.w);
        const size_t o = (size_t)r * NS_P + c4 * 4;
        *reinterpret_cast<__half2*>(hi + o) =
            __halves2half2(__float2half_rn(v.x), __float2half_rn(v.y));
        *reinterpret_cast<__half2*>(hi + o + 2) =
            __halves2half2(__float2half_rn(v.z), __float2half_rn(v.w));
    }
    #pragma unroll
    for (int off = 16; off; off >>= 1) acc += __shfl_down_sync(0xffffffffu, acc, off);
    __shared__ float ws[8];
    if ((tid & 31) == 0) ws[tid >> 5] = acc;
    __syncthreads();
    if (tid == 0 && real) {
        float s = 0.f;
        #pragma unroll
        for (int w = 0; w < 8; w++) s += ws[w];
        invdeg[r] = 1.f / (s + 1e-6f);
    }
}

__global__ void split_cols_k(const float* __restrict__ in, int ld, int col0,
                             __half* __restrict__ hi, __half* __restrict__ lo,
                             int M)
{
    const int r = blockIdx.x;
    const int c = threadIdx.x * 4;
    float4 v = make_float4(0.f, 0.f, 0.f, 0.f);
    if (r < M)
        v = *reinterpret_cast<const float4*>(in + (size_t)r * ld + col0 + c);
    __half h0 = __float2half_rn(v.x), h1 = __float2half_rn(v.y);
    __half h2 = __float2half_rn(v.z), h3 = __float2half_rn(v.w);
    const size_t o = (size_t)r * DD + c;
    *reinterpret_cast<__half2*>(hi + o)     = __halves2half2(h0, h1);
    *reinterpret_cast<__half2*>(hi + o + 2) = __halves2half2(h2, h3);
    *reinterpret_cast<__half2*>(lo + o) = __halves2half2(
        __float2half_rn(v.x - __half2float(h0)),
        __float2half_rn(v.y - __half2float(h1)));
    *reinterpret_cast<__half2*>(lo + o + 2) = __halves2half2(
        __float2half_rn(v.z - __half2float(h2)),
        __float2half_rn(v.w - __half2float(h3)));
}

__global__ void split_cols_hi_k(const float* __restrict__ in, int ld, int col0,
                                __half* __restrict__ hi, int M)
{
    const int r = blockIdx.x;
    const int c = threadIdx.x * 4;
    float4 v = make_float4(0.f, 0.f, 0.f, 0.f);
    if (r < M)
        v = *reinterpret_cast<const float4*>(in + (size_t)r * ld + col0 + c);
    const size_t o = (size_t)r * DD + c;
    *reinterpret_cast<__half2*>(hi + o) =
        __halves2half2(__float2half_rn(v.x), __float2half_rn(v.y));
    *reinterpret_cast<__half2*>(hi + o + 2) =
        __halves2half2(__float2half_rn(v.z), __float2half_rn(v.w));
}

__global__ void splitW_hi_k(const float* __restrict__ W,
                            const float* __restrict__ V,
                            __half* __restrict__ hi)
{
    const int row = blockIdx.x;           // 0 .. NL*512-1
    const int l = row >> 9, k = row & 511;
    const int n = threadIdx.x * 4;        // 256 threads -> 1024 cols
    const float* src = (n < 512) ? (W + ((size_t)l * DD + k) * DD + n)
                                 : (V + ((size_t)l * DD + k) * DD + n - 512);
    float4 v = *reinterpret_cast<const float4*>(src);
    const size_t o = (size_t)row * 1024 + n;
    *reinterpret_cast<__half2*>(hi + o) =
        __halves2half2(__float2half_rn(v.x), __float2half_rn(v.y));
    *reinterpret_cast<__half2*>(hi + o + 2) =
        __halves2half2(__float2half_rn(v.z), __float2half_rn(v.w));
}

// ---------------------------------------------------------------------------
// Column degrees
// ---------------------------------------------------------------------------
__global__ void colsum_part_k(const float* __restrict__ A, float* __restrict__ part)
{
    int s = blockIdx.x * blockDim.x + threadIdx.x;
    if (s >= NS) return;
    int chunk = blockIdx.y;
    const int rows = NR / COL_CHUNKS;
    const float* p = A + (size_t)(chunk * rows) * NS + s;
    float acc = 0.f;
    for (int r = 0; r < rows; r++) acc += p[(size_t)r * NS];
    part[chunk * NS + s] = acc;
}
__global__ void colsum_fin_k(const float* __restrict__ part, float* __restrict__ invdeg)
{
    int s = blockIdx.x * blockDim.x + threadIdx.x;
    if (s >= NS) return;
    float acc = 0.f;
    #pragma unroll
    for (int c = 0; c < COL_CHUNKS; c++) acc += part[c * NS + s];
    invdeg[s] = 1.f / (acc + 1e-6f);
}

// ---------------------------------------------------------------------------
// Host orchestration
// ---------------------------------------------------------------------------
extern "C" void kernel_launch(void* const* d_in, const int* in_sizes, int n_in,
                              void* d_out, int out_size)
{
    const float* h_s_in = (const float*)d_in[0];  // [NS, DD]
    const float* A      = (const float*)d_in[1];  // [NR, NS]
    const float* r_emb  = (const float*)d_in[2];  // [NR, DD]
    const float* Wr     = (const float*)d_in[3];  // [NL, DD, DD]
    const float* Ws     = (const float*)d_in[4];
    const float* Vr     = (const float*)d_in[5];
    const float* Vs     = (const float*)d_in[6];
    float* out = (float*)d_out;                   // [NR, DD]

    cudaFuncSetAttribute((const void*)hmma_gemm3_k,
                         cudaFuncAttributeMaxDynamicSharedMemorySize, SMEM_3TERM);
    cudaFuncSetAttribute((const void*)hmma_tall_k<0, 0>,
                         cudaFuncAttributeMaxDynamicSharedMemorySize, SMEM_TALL);
    cudaFuncSetAttribute((const void*)hmma_tall_k<0, 1>,
                         cudaFuncAttributeMaxDynamicSharedMemorySize, SMEM_TALL);
    cudaFuncSetAttribute((const void*)hmma_tall_k<0, 2>,
                         cudaFuncAttributeMaxDynamicSharedMemorySize, SMEM_TALL);
    cudaFuncSetAttribute((const void*)hmma_tall_k<0, 3>,
                         cudaFuncAttributeMaxDynamicSharedMemorySize, SMEM_TALL);
    cudaFuncSetAttribute((const void*)hmma_tall_k<1, 0>,
                         cudaFuncAttributeMaxDynamicSharedMemorySize, SMEM_TALL);

    float *invdr, *invds, *colpart, *fS, *tr, *partS;
    __half *Ahi, *hrhi, *hrlo, *hshi, *gshi, *grhi, *WShi, *Wrhi, *Wrlo, *Vrhi;
    cudaGetSymbolAddress((void**)&invdr,   g_invdeg_r);
    cudaGetSymbolAddress((void**)&invds,   g_invdeg_s);
    cudaGetSymbolAddress((void**)&colpart, g_colpart);
    cudaGetSymbolAddress((void**)&fS,    g_fS);
    cudaGetSymbolAddress((void**)&tr,    g_tr);
    cudaGetSymbolAddress((void**)&partS, g_partS);
    cudaGetSymbolAddress((void**)&Ahi,  g_Ahi);
    cudaGetSymbolAddress((void**)&hrhi, g_hrhi);
    cudaGetSymbolAddress((void**)&hrlo, g_hrlo);
    cudaGetSymbolAddress((void**)&hshi, g_hshi);
    cudaGetSymbolAddress((void**)&gshi, g_gshi);
    cudaGetSymbolAddress((void**)&grhi, g_grhi);
    cudaGetSymbolAddress((void**)&WShi, g_WShi);
    cudaGetSymbolAddress((void**)&Wrhi, g_Wrhi);
    cudaGetSymbolAddress((void**)&Wrlo, g_Wrlo);
    cudaGetSymbolAddress((void**)&Vrhi, g_Vrhi);

    // 1: h_s hi split  2: [Ws|Vs] hi  3: Wr hi/lo  4: fS GEMM (profiled)
    split_cols_hi_k<<<NS_P, 128>>>(h_s_in, DD, 0, hshi, NS);
    splitW_hi_k<<<NL * DD, 256>>>(Ws, Vs, WShi);
    split_cols_k<<<NL * DD, 128>>>(Wr, DD, 0, Wrhi, Wrlo, NL * DD);

    for (int l = 0; l < NL; l++) {
        const bool last = (l == NL - 1);
        const int NW = last ? 512 : 1024;

        // fS = h_s @ [Ws|Vs][l] -> fp32 [NS, 1024]   (tall 1-term)
        hmma_tall_k<0, 0><<<dim3(NW / 128, NS_P / 64, 1), 256, SMEM_TALL>>>(
            NS, DD / 64, hshi, DD,
            WShi + (size_t)l * DD * 1024, 1024, fS, 1024, 0,
            nullptr, nullptr, 0, nullptr);

        if (l == 0) {
            split_cols_hi_k<<<NL * DD, 128>>>(Vr, DD, 0, Vrhi, NL * DD);
            split_cols_k<<<NR_P, 128>>>(r_emb, DD, 0, hrhi, hrlo, NR);
            splitA_hi_k<<<NR_P, 256>>>(A, Ahi, invdr);
            colsum_part_k<<<dim3((NS + 255) / 256, COL_CHUNKS), 256>>>(A, colpart);
            colsum_fin_k<<<(NS + 255) / 256, 256>>>(colpart, invds);
        }

        // tr = h_r @ Wr[l] -> fp32 [NR, 512]   (3-term, precision-critical)
        hmma_gemm3_k<<<dim3(4, NR_P / 128, 1), 256, SMEM_3TERM>>>(
            NR, DD / 32, hrhi, hrlo, DD,
            Wrhi + (size_t)l * DD * DD, Wrlo + (size_t)l * DD * DD, DD,
            tr, DD);

        // gs -> fp16 hi (aggregation operand)
        split_cols_hi_k<<<NS_P, 128>>>(fS, 1024, 0, gshi, NS);

        if (!last) {
            // gr = h_r @ Vr[l] -> fp16 direct (uses OLD h_r, before bigR)
            hmma_tall_k<0, 1><<<dim3(4, NR_P / 64, 1), 256, SMEM_TALL>>>(
                NR_P, DD / 64, hrhi, DD,
                Vrhi + (size_t)l * DD * DD, DD, grhi, DD, 0,
                nullptr, nullptr, 0, nullptr);
        }

        // bigR fused: h_r' = relu(invdeg_r * (A @ gs) + tr), full-K tall
        if (last) {
            hmma_tall_k<0, 2><<<dim3(4, NR_P / 64, 1), 256, SMEM_TALL>>>(
                NR, NS_P / 64, Ahi, NS_P, gshi, DD, out, DD, 0,
                invdr, tr, DD, nullptr);
        } else {
            hmma_tall_k<0, 3><<<dim3(4, NR_P / 64, 1), 256, SMEM_TALL>>>(
                NR, NS_P / 64, Ahi, NS_P, gshi, DD, hrhi, DD, 0,
                invdr, tr, DD, hrlo);

            // bigS: partS = A^T @ gr (tall, A read transposed, split-K)
            hmma_tall_k<1, 0><<<dim3(4, NS_P / 64, KSPLIT_S), 256, SMEM_TALL>>>(
                NS, KR_P / 64, Ahi, NS_P, grhi, DD,
                partS, DD, (size_t)NS * DD,
                nullptr, nullptr, 0, nullptr);

            // h_s' = relu(invdeg_s * (A^T @ gr) + ts), hi-only
            reduce_epi_hi_k<<<(NS_P * 128 + 255) / 256, 256>>>(
                NS, NS_P, KSPLIT_S, partS, (size_t)NS * DD, invds,
                fS + 512, 1024, hshi);
        }
    }
}

// round 15
// speedup vs baseline: 1.0377x; 1.0325x over previous
#include <cuda_runtime.h>
#include <cuda_fp16.h>
#include <cstdint>

// ---------------------------------------------------------------------------
// Problem constants
// ---------------------------------------------------------------------------
#define NR 20000          // readings
#define NS 5000           // skills
#define DD 512            // embedding dim
#define NL 3              // layers
#define NR_P 20096        // NR padded to 128
#define NS_P 5120         // NS padded to 128
#define KR_P 20032        // NR padded to 64 (K dim of A^T GEMM)
#define COL_CHUNKS 16
#define KSPLIT_R 4        // split-K for A@gs   (grid 4*157*4 = 2512)
#define KSPLIT_S 4        // split-K for A^T@gr (grid 4*40*4  = 640)

// ---------------------------------------------------------------------------
// Device scratch (no cudaMalloc allowed)
// ---------------------------------------------------------------------------
__device__ float g_invdeg_r[NR];
__device__ float g_invdeg_s[NS];
__device__ float g_colpart[COL_CHUNKS * NS];

__device__ __align__(16) __half g_Ahi[(size_t)NR_P * NS_P];
__device__ __align__(16) __half g_hrhi[(size_t)NR_P * DD];
__device__ __align__(16) __half g_hrlo[(size_t)NR_P * DD];
__device__ __align__(16) __half g_hshi[(size_t)NS_P * DD];
__device__ __align__(16) __half g_gshi[(size_t)NS_P * DD];
__device__ __align__(16) __half g_grhi[(size_t)NR_P * DD];
__device__ __align__(16) __half g_WShi[(size_t)NL * DD * 1024];  // [Ws|Vs] hi
__device__ __align__(16) __half g_Wrhi[(size_t)NL * DD * DD];
__device__ __align__(16) __half g_Wrlo[(size_t)NL * DD * DD];
__device__ __align__(16) __half g_Vrhi[(size_t)NL * DD * DD];

__device__ float g_fS[(size_t)NS * 1024];            // [gs | ts]
__device__ float g_tr[(size_t)NR * DD];
__device__ float g_partR[(size_t)KSPLIT_R * NR * DD];
__device__ float g_partS[(size_t)KSPLIT_S * NS * DD];

// ---------------------------------------------------------------------------
// PTX helpers (Ampere-era ISA: compiles for plain compute_103 target)
// ---------------------------------------------------------------------------
__device__ __forceinline__ uint32_t smem_u32(const void* p) {
    uint32_t a;
    asm("{ .reg .u64 t; cvta.to.shared.u64 t, %1; cvt.u32.u64 %0, t; }"
        : "=r"(a) : "l"(p));
    return a;
}
__device__ __forceinline__ void cp16(uint32_t dst, const void* src) {
    asm volatile("cp.async.cg.shared.global [%0], [%1], 16;"
                 :: "r"(dst), "l"(src) : "memory");
}
__device__ __forceinline__ void cp_commit() {
    asm volatile("cp.async.commit_group;" ::: "memory");
}
template <int N>
__device__ __forceinline__ void cp_wait() {
    asm volatile("cp.async.wait_group %0;" :: "n"(N) : "memory");
}
__device__ __forceinline__ void ldsm4(uint32_t& r0, uint32_t& r1,
                                      uint32_t& r2, uint32_t& r3, uint32_t a) {
    asm volatile("ldmatrix.sync.aligned.m8n8.x4.shared.b16 {%0,%1,%2,%3}, [%4];"
                 : "=r"(r0), "=r"(r1), "=r"(r2), "=r"(r3) : "r"(a));
}
__device__ __forceinline__ void ldsm4t(uint32_t& r0, uint32_t& r1,
                                       uint32_t& r2, uint32_t& r3, uint32_t a) {
    asm volatile("ldmatrix.sync.aligned.m8n8.x4.trans.shared.b16 {%0,%1,%2,%3}, [%4];"
                 : "=r"(r0), "=r"(r1), "=r"(r2), "=r"(r3) : "r"(a));
}
__device__ __forceinline__ void mma16816(float* d, const uint32_t* a,
                                         const uint32_t* b) {
    asm volatile(
        "mma.sync.aligned.m16n8k16.row.col.f32.f16.f16.f32 "
        "{%0,%1,%2,%3}, {%4,%5,%6,%7}, {%8,%9}, {%0,%1,%2,%3};"
        : "+f"(d[0]), "+f"(d[1]), "+f"(d[2]), "+f"(d[3])
        : "r"(a[0]), "r"(a[1]), "r"(a[2]), "r"(a[3]), "r"(b[0]), "r"(b[1]));
}
// A-normal tile [128m x BKk] (BK/8 segments of 2KB). MUL=2 for BK32,
// MUL=1 for BK64. Conflict-free for cp.async stores and ldmatrix phases.
__device__ __forceinline__ uint32_t swzA(int r, int c16, int mul) {
    return (uint32_t)((c16 << 11) + ((r >> 3) << 7) + (((r + mul * c16) & 7) << 4));
}
// K-major tile [BKk x 128cols] (256B rows): XOR swizzle, conflict-free for
// cp.async stores and ldmatrix phases.
__device__ __forceinline__ uint32_t swz_kn(int r, int c) {
    return (uint32_t)(r * 256 + ((c & 8) << 4) + (((c ^ r) & 7) << 4));
}

// ---------------------------------------------------------------------------
// Stage loader. Layout: Ahi(+0) [Alo(+HALF)] Bhi(+BOFF) [Blo(+BOFF+HALF)]
// ---------------------------------------------------------------------------
template <int A_TRANS, int A_SPLIT, int B_SPLIT, int BK64>
__device__ __forceinline__ void load_stage(uint32_t sb,
    const __half* __restrict__ Ahi, const __half* __restrict__ Alo,
    int lda, int bm,
    const __half* __restrict__ Bhi, const __half* __restrict__ Blo,
    int ldb, int bn, int k0, int tid)
{
    constexpr uint32_t HALF = BK64 ? 16384u : 8192u;
    constexpr uint32_t BOFF = HALF * (1 + A_SPLIT);
    constexpr int ITER = BK64 ? 4 : 2;
    constexpr int CMASK = BK64 ? 7 : 3;
    constexpr int CSH   = BK64 ? 3 : 2;
    constexpr int MUL   = BK64 ? 1 : 2;
    #pragma unroll
    for (int i = 0; i < ITER; i++) {
        const int idx = tid + i * 256;
        const int r = idx >> 4, c = idx & 15;
        const uint32_t so = swz_kn(r, c);
        const size_t bo = (size_t)(k0 + r) * ldb + bn + c * 8;
        cp16(sb + BOFF + so, Bhi + bo);
        if (B_SPLIT) cp16(sb + BOFF + HALF + so, Blo + bo);
        if (A_TRANS) {
            const size_t ao = (size_t)(k0 + r) * lda + bm + c * 8;
            cp16(sb + so, Ahi + ao);
            if (A_SPLIT) cp16(sb + HALF + so, Alo + ao);
        } else {
            const int c16 = idx & CMASK, ra = idx >> CSH;
            const uint32_t soA = swzA(ra, c16, MUL);
            const size_t ao = (size_t)(bm + ra) * lda + k0 + c16 * 8;
            cp16(sb + soA, Ahi + ao);
            if (A_SPLIT) cp16(sb + HALF + soA, Alo + ao);
        }
    }
}

// ---------------------------------------------------------------------------
// HMMA GEMM (R12-proven): C[M,N] = op(A)[M,K] @ B[K,N]
//   Terms kept: Ah*Bh (+Ah*Bl if B_SPLIT) (+Al*Bh if A_SPLIT).
//   A_TRANS=1 reads A from [K,M] row-major. BK64: 64-wide K chunks.
//   OUT_HALF=1: write fp16. CTA 128x128, 3-stage cp.async, 8 warps 2Mx4N,
//   2 CTAs/SM. Split-K over gridDim.z -> plain partials.
// ---------------------------------------------------------------------------
template <int A_TRANS, int A_SPLIT, int B_SPLIT, int BK64, int OUT_HALF>
__global__ void __launch_bounds__(256, 2)
hmma_gemm_k(int M, int Kc,
            const __half* __restrict__ Ahi, const __half* __restrict__ Alo,
            int lda,
            const __half* __restrict__ Bhi, const __half* __restrict__ Blo,
            int ldb,
            void* __restrict__ Cv, int ldc, size_t part_stride)
{
    constexpr uint32_t HALF = BK64 ? 16384u : 8192u;
    constexpr uint32_t BOFF = HALF * (1 + A_SPLIT);
    constexpr int STAGE = (int)HALF * (2 + A_SPLIT + B_SPLIT);
    constexpr int NST   = 3;
    constexpr int KSUB  = BK64 ? 4 : 2;
    constexpr int KW    = BK64 ? 64 : 32;
    constexpr int MUL   = BK64 ? 1 : 2;

    extern __shared__ char sm[];
    const uint32_t smb = smem_u32(sm);
    const int tid  = threadIdx.x;
    const int wid  = tid >> 5;
    const int lane = tid & 31;
    const int warp_m = wid & 1;
    const int warp_n = wid >> 1;
    const int bm = blockIdx.y * 128;
    const int bn = blockIdx.x * 128;

    const int P = gridDim.z, p = blockIdx.z;
    const int kbase = Kc / P, krem = Kc - kbase * P;
    const int kc0 = p * kbase + (p < krem ? p : krem);
    const int kcn = kbase + (p < krem ? 1 : 0);

    float acc[4][4][4];
    #pragma unroll
    for (int mf = 0; mf < 4; mf++)
        #pragma unroll
        for (int nt = 0; nt < 4; nt++)
            #pragma unroll
            for (int i = 0; i < 4; i++) acc[mf][nt][i] = 0.f;

    #pragma unroll
    for (int s = 0; s < NST - 1; s++) {
        if (s < kcn)
            load_stage<A_TRANS, A_SPLIT, B_SPLIT, BK64>(
                smb + s * STAGE, Ahi, Alo, lda, bm,
                Bhi, Blo, ldb, bn, (kc0 + s) * KW, tid);
        cp_commit();
    }

    const int aN_r  = warp_m * 64 + (lane & 15);
    const int aN_ch = lane >> 4;
    const int aT_r  = (lane & 7) + ((lane >> 4) << 3);
    const int aT_cb = warp_m * 8 + ((lane >> 3) & 1);
    const int b_r   = lane & 15;
    const int b_cb  = warp_n * 4 + (lane >> 4);

    for (int ci = 0; ci < kcn; ci++) {
        cp_wait<NST - 2>();
        __syncthreads();
        if (ci + NST - 1 < kcn)
            load_stage<A_TRANS, A_SPLIT, B_SPLIT, BK64>(
                smb + ((ci + NST - 1) % NST) * STAGE, Ahi, Alo, lda, bm,
                Bhi, Blo, ldb, bn, (kc0 + ci + NST - 1) * KW, tid);
        cp_commit();

        const uint32_t sb = smb + (ci % NST) * STAGE;
        #pragma unroll
        for (int ks = 0; ks < KSUB; ks++) {
            uint32_t ah[4][4], al[4][4], bh[2][4], bl[2][4];
            #pragma unroll
            for (int mf = 0; mf < 4; mf++) {
                if (A_TRANS) {
                    const uint32_t ad =
                        sb + swz_kn(ks * 16 + aT_r, aT_cb + mf * 2);
                    ldsm4t(ah[mf][0], ah[mf][1], ah[mf][2], ah[mf][3], ad);
                    if (A_SPLIT)
                        ldsm4t(al[mf][0], al[mf][1], al[mf][2], al[mf][3],
                               ad + HALF);
                } else {
                    const uint32_t ad =
                        sb + swzA(aN_r + mf * 16, ks * 2 + aN_ch, MUL);
                    ldsm4(ah[mf][0], ah[mf][1], ah[mf][2], ah[mf][3], ad);
                    if (A_SPLIT)
                        ldsm4(al[mf][0], al[mf][1], al[mf][2], al[mf][3],
                              ad + HALF);
                }
            }
            #pragma unroll
            for (int np = 0; np < 2; np++) {
                const uint32_t bd =
                    sb + BOFF + swz_kn(ks * 16 + b_r, b_cb + np * 2);
                ldsm4t(bh[np][0], bh[np][1], bh[np][2], bh[np][3], bd);
                if (B_SPLIT)
                    ldsm4t(bl[np][0], bl[np][1], bl[np][2], bl[np][3],
                           bd + HALF);
            }
            #pragma unroll
            for (int mf = 0; mf < 4; mf++) {
                #pragma unroll
                for (int np = 0; np < 2; np++) {
                    mma16816(acc[mf][np * 2],     ah[mf], &bh[np][0]);
                    mma16816(acc[mf][np * 2 + 1], ah[mf], &bh[np][2]);
                    if (B_SPLIT) {
                        mma16816(acc[mf][np * 2],     ah[mf], &bl[np][0]);
                        mma16816(acc[mf][np * 2 + 1], ah[mf], &bl[np][2]);
                    }
                    if (A_SPLIT) {
                        mma16816(acc[mf][np * 2],     al[mf], &bh[np][0]);
                        mma16816(acc[mf][np * 2 + 1], al[mf], &bh[np][2]);
                    }
                }
            }
        }
    }

    const int row_in = lane >> 2;
    const int col_in = (lane & 3) * 2;
    #pragma unroll
    for (int mf = 0; mf < 4; mf++) {
        #pragma unroll
        for (int h2 = 0; h2 < 2; h2++) {
            const int m = bm + warp_m * 64 + mf * 16 + row_in + h2 * 8;
            if (m >= M) continue;
            #pragma unroll
            for (int nt = 0; nt < 4; nt++) {
                const int n = bn + warp_n * 32 + nt * 8 + col_in;
                const float v0 = acc[mf][nt][h2 * 2 + 0];
                const float v1 = acc[mf][nt][h2 * 2 + 1];
                if (OUT_HALF) {
                    __half* C = (__half*)Cv + part_stride * (size_t)p;
                    *reinterpret_cast<__half2*>(C + (size_t)m * ldc + n) =
                        __halves2half2(__float2half_rn(v0), __float2half_rn(v1));
                } else {
                    float* C = (float*)Cv + part_stride * (size_t)p;
                    float2 o; o.x = v0; o.y = v1;
                    *reinterpret_cast<float2*>(C + (size_t)m * ldc + n) = o;
                }
            }
        }
    }
}

#define SMEM_3TERM (3 * 32768)   // BK32 3-term
#define SMEM_1T64  (3 * 32768)   // BK64 1-term

// ---------------------------------------------------------------------------
// Combined small GEMM: two independent 1-term BK64 A-normal GEMMs (K=512)
// in ONE launch, decoded from flat blockIdx.x.
//   Problem 1 (first count1 blocks):  C1(fp32)[M1 x n1tiles*128] = A1 @ B1
//   Problem 2 (remaining blocks):     C2(fp16)[M2 x n2tiles*128] = A2 @ B2
// Same mainloop as hmma_gemm_k<0,0,0,1,*>.
// ---------------------------------------------------------------------------
__global__ void __launch_bounds__(256, 2)
hmma_combo_k(int count1, int n1tiles, int M1,
             const __half* __restrict__ A1, int lda1,
             const __half* __restrict__ B1, int ldb1,
             float* __restrict__ C1, int ldc1,
             int n2tiles, int M2,
             const __half* __restrict__ A2, int lda2,
             const __half* __restrict__ B2, int ldb2,
             __half* __restrict__ C2, int ldc2,
             int Kc)
{
    constexpr int STAGE = 32768, NST = 3;
    extern __shared__ char sm[];
    const uint32_t smb = smem_u32(sm);
    const int tid  = threadIdx.x;
    const int wid  = tid >> 5;
    const int lane = tid & 31;
    const int warp_m = wid & 1;
    const int warp_n = wid >> 1;

    const int id = blockIdx.x;
    const bool p2 = (id >= count1);
    int bm, bn, M, lda, ldb;
    const __half *Ahi, *Bhi;
    if (!p2) {
        bn = (id % n1tiles) * 128; bm = (id / n1tiles) * 128;
        M = M1; Ahi = A1; lda = lda1; Bhi = B1; ldb = ldb1;
    } else {
        const int id2 = id - count1;
        bn = (id2 % n2tiles) * 128; bm = (id2 / n2tiles) * 128;
        M = M2; Ahi = A2; lda = lda2; Bhi = B2; ldb = ldb2;
    }

    float acc[4][4][4];
    #pragma unroll
    for (int mf = 0; mf < 4; mf++)
        #pragma unroll
        for (int nt = 0; nt < 4; nt++)
            #pragma unroll
            for (int i = 0; i < 4; i++) acc[mf][nt][i] = 0.f;

    #pragma unroll
    for (int s = 0; s < NST - 1; s++) {
        if (s < Kc)
            load_stage<0, 0, 0, 1>(smb + s * STAGE, Ahi, nullptr, lda, bm,
                                   Bhi, nullptr, ldb, bn, s * 64, tid);
        cp_commit();
    }

    const int aN_r  = warp_m * 64 + (lane & 15);
    const int aN_ch = lane >> 4;
    const int b_r   = lane & 15;
    const int b_cb  = warp_n * 4 + (lane >> 4);

    for (int ci = 0; ci < Kc; ci++) {
        cp_wait<NST - 2>();
        __syncthreads();
        if (ci + NST - 1 < Kc)
            load_stage<0, 0, 0, 1>(smb + ((ci + NST - 1) % NST) * STAGE,
                                   Ahi, nullptr, lda, bm,
                                   Bhi, nullptr, ldb, bn,
                                   (ci + NST - 1) * 64, tid);
        cp_commit();

        const uint32_t sb = smb + (ci % NST) * STAGE;
        #pragma unroll
        for (int ks = 0; ks < 4; ks++) {
            uint32_t ah[4][4], bh[2][4];
            #pragma unroll
            for (int mf = 0; mf < 4; mf++) {
                const uint32_t ad =
                    sb + swzA(aN_r + mf * 16, ks * 2 + aN_ch, 1);
                ldsm4(ah[mf][0], ah[mf][1], ah[mf][2], ah[mf][3], ad);
            }
            #pragma unroll
            for (int np = 0; np < 2; np++) {
                const uint32_t bd =
                    sb + 16384 + swz_kn(ks * 16 + b_r, b_cb + np * 2);
                ldsm4t(bh[np][0], bh[np][1], bh[np][2], bh[np][3], bd);
            }
            #pragma unroll
            for (int mf = 0; mf < 4; mf++) {
                #pragma unroll
                for (int np = 0; np < 2; np++) {
                    mma16816(acc[mf][np * 2],     ah[mf], &bh[np][0]);
                    mma16816(acc[mf][np * 2 + 1], ah[mf], &bh[np][2]);
                }
            }
        }
    }

    const int row_in = lane >> 2;
    const int col_in = (lane & 3) * 2;
    #pragma unroll
    for (int mf = 0; mf < 4; mf++) {
        #pragma unroll
        for (int h2 = 0; h2 < 2; h2++) {
            const int m = bm + warp_m * 64 + mf * 16 + row_in + h2 * 8;
            if (m >= M) continue;
            #pragma unroll
            for (int nt = 0; nt < 4; nt++) {
                const int n = bn + warp_n * 32 + nt * 8 + col_in;
                const float v0 = acc[mf][nt][h2 * 2 + 0];
                const float v1 = acc[mf][nt][h2 * 2 + 1];
                if (!p2) {
                    float2 o; o.x = v0; o.y = v1;
                    *reinterpret_cast<float2*>(C1 + (size_t)m * ldc1 + n) = o;
                } else {
                    *reinterpret_cast<__half2*>(C2 + (size_t)m * ldc2 + n) =
                        __halves2half2(__float2half_rn(v0), __float2half_rn(v1));
                }
            }
        }
    }
}

// ---------------------------------------------------------------------------
// reduce + epilogue: v = relu(invdeg[m] * sum_p part[p] + add[m,n])
//   MODE 0: fp32 out (rows < M). MODE 1: fp16 hi+lo. MODE 2: fp16 hi only.
// ---------------------------------------------------------------------------
template <int MODE>
__global__ void reduce_epi_k(int M, int MP, int P,
                             const float* __restrict__ part, size_t pstride,
                             const float* __restrict__ invdeg,
                             const float* __restrict__ add, int ld_add,
                             float* __restrict__ out32,
                             __half* __restrict__ hi, __half* __restrict__ lo)
{
    int idx = blockIdx.x * 256 + threadIdx.x;   // over MP * 128 float4s
    if (idx >= MP * 128) return;
    int m = idx >> 7, q = (idx & 127) << 2;
    float4 o = make_float4(0.f, 0.f, 0.f, 0.f);
    if (m < M) {
        float4 s = make_float4(0.f, 0.f, 0.f, 0.f);
        for (int pp = 0; pp < P; pp++) {
            const float4 v = *reinterpret_cast<const float4*>(
                part + pp * pstride + (size_t)m * DD + q);
            s.x += v.x; s.y += v.y; s.z += v.z; s.w += v.w;
        }
        const float sc = invdeg[m];
        const float4 a = *reinterpret_cast<const float4*>(
            add + (size_t)m * ld_add + q);
        o.x = fmaxf(fmaf(sc, s.x, a.x), 0.f);
        o.y = fmaxf(fmaf(sc, s.y, a.y), 0.f);
        o.z = fmaxf(fmaf(sc, s.z, a.z), 0.f);
        o.w = fmaxf(fmaf(sc, s.w, a.w), 0.f);
    }
    if (MODE == 0) {
        if (m < M)
            *reinterpret_cast<float4*>(out32 + (size_t)m * DD + q) = o;
    } else {
        __half h0 = __float2half_rn(o.x), h1 = __float2half_rn(o.y);
        __half h2 = __float2half_rn(o.z), h3 = __float2half_rn(o.w);
        const size_t off = (size_t)m * DD + q;
        *reinterpret_cast<__half2*>(hi + off)     = __halves2half2(h0, h1);
        *reinterpret_cast<__half2*>(hi + off + 2) = __halves2half2(h2, h3);
        if (MODE == 1) {
            *reinterpret_cast<__half2*>(lo + off) = __halves2half2(
                __float2half_rn(o.x - __half2float(h0)),
                __float2half_rn(o.y - __half2float(h1)));
            *reinterpret_cast<__half2*>(lo + off + 2) = __halves2half2(
                __float2half_rn(o.z - __half2float(h2)),
                __float2half_rn(o.w - __half2float(h3)));
        }
    }
}

// ---------------------------------------------------------------------------
// Conversions
// ---------------------------------------------------------------------------
__global__ void splitA_hi_k(const float* __restrict__ A,
                            __half* __restrict__ hi,
                            float* __restrict__ invdeg)
{
    const int r = blockIdx.x;           // 0..NR_P-1
    const bool real = (r < NR);
    const int tid = threadIdx.x;        // 256
    float acc = 0.f;
    for (int c4 = tid; c4 < NS_P / 4; c4 += 256) {
        float4 v = make_float4(0.f, 0.f, 0.f, 0.f);
        if (real && c4 < NS / 4)
            v = *reinterpret_cast<const float4*>(A + (size_t)r * NS + c4 * 4);
        acc += (v.x + v.y) + (v.z + v.w);
        const size_t o = (size_t)r * NS_P + c4 * 4;
        *reinterpret_cast<__half2*>(hi + o) =
            __halves2half2(__float2half_rn(v.x), __float2half_rn(v.y));
        *reinterpret_cast<__half2*>(hi + o + 2) =
            __halves2half2(__float2half_rn(v.z), __float2half_rn(v.w));
    }
    #pragma unroll
    for (int off = 16; off; off >>= 1) acc += __shfl_down_sync(0xffffffffu, acc, off);
    __shared__ float ws[8];
    if ((tid & 31) == 0) ws[tid >> 5] = acc;
    __syncthreads();
    if (tid == 0 && real) {
        float s = 0.f;
        #pragma unroll
        for (int w = 0; w < 8; w++) s += ws[w];
        invdeg[r] = 1.f / (s + 1e-6f);
    }
}

__global__ void split_cols_k(const float* __restrict__ in, int ld, int col0,
                             __half* __restrict__ hi, __half* __restrict__ lo,
                             int M)
{
    const int r = blockIdx.x;
    const int c = threadIdx.x * 4;
    float4 v = make_float4(0.f, 0.f, 0.f, 0.f);
    if (r < M)
        v = *reinterpret_cast<const float4*>(in + (size_t)r * ld + col0 + c);
    __half h0 = __float2half_rn(v.x), h1 = __float2half_rn(v.y);
    __half h2 = __float2half_rn(v.z), h3 = __float2half_rn(v.w);
    const size_t o = (size_t)r * DD + c;
    *reinterpret_cast<__half2*>(hi + o)     = __halves2half2(h0, h1);
    *reinterpret_cast<__half2*>(hi + o + 2) = __halves2half2(h2, h3);
    *reinterpret_cast<__half2*>(lo + o) = __halves2half2(
        __float2half_rn(v.x - __half2float(h0)),
        __float2half_rn(v.y - __half2float(h1)));
    *reinterpret_cast<__half2*>(lo + o + 2) = __halves2half2(
        __float2half_rn(v.z - __half2float(h2)),
        __float2half_rn(v.w - __half2float(h3)));
}

__global__ void split_cols_hi_k(const float* __restrict__ in, int ld, int col0,
                                __half* __restrict__ hi, int M)
{
    const int r = blockIdx.x;
    const int c = threadIdx.x * 4;
    float4 v = make_float4(0.f, 0.f, 0.f, 0.f);
    if (r < M)
        v = *reinterpret_cast<const float4*>(in + (size_t)r * ld + col0 + c);
    const size_t o = (size_t)r * DD + c;
    *reinterpret_cast<__half2*>(hi + o) =
        __halves2half2(__float2half_rn(v.x), __float2half_rn(v.y));
    *reinterpret_cast<__half2*>(hi + o + 2) =
        __halves2half2(__float2half_rn(v.z), __float2half_rn(v.w));
}

__global__ void splitW_hi_k(const float* __restrict__ W,
                            const float* __restrict__ V,
                            __half* __restrict__ hi)
{
    const int row = blockIdx.x;           // 0 .. NL*512-1
    const int l = row >> 9, k = row & 511;
    const int n = threadIdx.x * 4;        // 256 threads -> 1024 cols
    const float* src = (n < 512) ? (W + ((size_t)l * DD + k) * DD + n)
                                 : (V + ((size_t)l * DD + k) * DD + n - 512);
    float4 v = *reinterpret_cast<const float4*>(src);
    const size_t o = (size_t)row * 1024 + n;
    *reinterpret_cast<__half2*>(hi + o) =
        __halves2half2(__float2half_rn(v.x), __float2half_rn(v.y));
    *reinterpret_cast<__half2*>(hi + o + 2) =
        __halves2half2(__float2half_rn(v.z), __float2half_rn(v.w));
}

// ---------------------------------------------------------------------------
// Column degrees
// ---------------------------------------------------------------------------
__global__ void colsum_part_k(const float* __restrict__ A, float* __restrict__ part)
{
    int s = blockIdx.x * blockDim.x + threadIdx.x;
    if (s >= NS) return;
    int chunk = blockIdx.y;
    const int rows = NR / COL_CHUNKS;
    const float* p = A + (size_t)(chunk * rows) * NS + s;
    float acc = 0.f;
    for (int r = 0; r < rows; r++) acc += p[(size_t)r * NS];
    part[chunk * NS + s] = acc;
}
__global__ void colsum_fin_k(const float* __restrict__ part, float* __restrict__ invdeg)
{
    int s = blockIdx.x * blockDim.x + threadIdx.x;
    if (s >= NS) return;
    float acc = 0.f;
    #pragma unroll
    for (int c = 0; c < COL_CHUNKS; c++) acc += part[c * NS + s];
    invdeg[s] = 1.f / (acc + 1e-6f);
}

// ---------------------------------------------------------------------------
// Host orchestration
// ---------------------------------------------------------------------------
extern "C" void kernel_launch(void* const* d_in, const int* in_sizes, int n_in,
                              void* d_out, int out_size)
{
    const float* h_s_in = (const float*)d_in[0];  // [NS, DD]
    const float* A      = (const float*)d_in[1];  // [NR, NS]
    const float* r_emb  = (const float*)d_in[2];  // [NR, DD]
    const float* Wr     = (const float*)d_in[3];  // [NL, DD, DD]
    const float* Ws     = (const float*)d_in[4];
    const float* Vr     = (const float*)d_in[5];
    const float* Vs     = (const float*)d_in[6];
    float* out = (float*)d_out;                   // [NR, DD]

    cudaFuncSetAttribute((const void*)hmma_gemm_k<0, 1, 1, 0, 0>,
                         cudaFuncAttributeMaxDynamicSharedMemorySize, SMEM_3TERM);
    cudaFuncSetAttribute((const void*)hmma_gemm_k<0, 0, 0, 1, 0>,
                         cudaFuncAttributeMaxDynamicSharedMemorySize, SMEM_1T64);
    cudaFuncSetAttribute((const void*)hmma_gemm_k<1, 0, 0, 1, 0>,
                         cudaFuncAttributeMaxDynamicSharedMemorySize, SMEM_1T64);
    cudaFuncSetAttribute((const void*)hmma_combo_k,
                         cudaFuncAttributeMaxDynamicSharedMemorySize, SMEM_1T64);

    float *invdr, *invds, *colpart, *fS, *tr, *partR, *partS;
    __half *Ahi, *hrhi, *hrlo, *hshi, *gshi, *grhi, *WShi, *Wrhi, *Wrlo, *Vrhi;
    cudaGetSymbolAddress((void**)&invdr,   g_invdeg_r);
    cudaGetSymbolAddress((void**)&invds,   g_invdeg_s);
    cudaGetSymbolAddress((void**)&colpart, g_colpart);
    cudaGetSymbolAddress((void**)&fS,    g_fS);
    cudaGetSymbolAddress((void**)&tr,    g_tr);
    cudaGetSymbolAddress((void**)&partR, g_partR);
    cudaGetSymbolAddress((void**)&partS, g_partS);
    cudaGetSymbolAddress((void**)&Ahi,  g_Ahi);
    cudaGetSymbolAddress((void**)&hrhi, g_hrhi);
    cudaGetSymbolAddress((void**)&hrlo, g_hrlo);
    cudaGetSymbolAddress((void**)&hshi, g_hshi);
    cudaGetSymbolAddress((void**)&gshi, g_gshi);
    cudaGetSymbolAddress((void**)&grhi, g_grhi);
    cudaGetSymbolAddress((void**)&WShi, g_WShi);
    cudaGetSymbolAddress((void**)&Wrhi, g_Wrhi);
    cudaGetSymbolAddress((void**)&Wrlo, g_Wrlo);
    cudaGetSymbolAddress((void**)&Vrhi, g_Vrhi);

    // --- one-time conversions & degrees ---
    split_cols_hi_k<<<NS_P, 128>>>(h_s_in, DD, 0, hshi, NS);
    splitW_hi_k<<<NL * DD, 256>>>(Ws, Vs, WShi);
    split_cols_k<<<NL * DD, 128>>>(Wr, DD, 0, Wrhi, Wrlo, NL * DD);
    split_cols_hi_k<<<NL * DD, 128>>>(Vr, DD, 0, Vrhi, NL * DD);
    split_cols_k<<<NR_P, 128>>>(r_emb, DD, 0, hrhi, hrlo, NR);
    splitA_hi_k<<<NR_P, 256>>>(A, Ahi, invdr);
    colsum_part_k<<<dim3((NS + 255) / 256, COL_CHUNKS), 256>>>(A, colpart);
    colsum_fin_k<<<(NS + 255) / 256, 256>>>(colpart, invds);

    for (int l = 0; l < NL; l++) {
        const bool last = (l == NL - 1);
        const int n1tiles = last ? 4 : 8;       // fS width tiles (512 or 1024)
        const int count1  = n1tiles * (NS_P / 128);
        const int count2  = last ? 0 : 4 * (NR_P / 128);

        // fS = h_s @ [Ws|Vs][l]  AND (if !last)  gr = h_r @ Vr[l]  (fused)
        hmma_combo_k<<<count1 + count2, 256, SMEM_1T64>>>(
            count1, n1tiles, NS,
            hshi, DD, WShi + (size_t)l * DD * 1024, 1024, fS, 1024,
            4, NR_P,
            hrhi, DD, Vrhi + (size_t)l * DD * DD, DD, grhi, DD,
            DD / 64);

        // tr = h_r @ Wr[l] -> fp32 [NR, 512]   (3-term, precision-critical)
        hmma_gemm_k<0, 1, 1, 0, 0><<<dim3(4, NR_P / 128, 1), 256, SMEM_3TERM>>>(
            NR, DD / 32, hrhi, hrlo, DD,
            Wrhi + (size_t)l * DD * DD, Wrlo + (size_t)l * DD * DD, DD,
            tr, DD, 0);

        // gs -> fp16 hi (aggregation operand)
        split_cols_hi_k<<<NS_P, 128>>>(fS, 1024, 0, gshi, NS);

        // bigR: partR = A @ gs (1-term BK64, split-K)
        hmma_gemm_k<0, 0, 0, 1, 0><<<dim3(4, NR_P / 128, KSPLIT_R), 256, SMEM_1T64>>>(
            NR, NS_P / 64, Ahi, nullptr, NS_P, gshi, nullptr, DD,
            partR, DD, (size_t)NR * DD);

        // h_r' = relu(invdeg_r * (A @ gs) + tr)
        if (last) {
            reduce_epi_k<0><<<(NR * 128 + 255) / 256, 256>>>(
                NR, NR, KSPLIT_R, partR, (size_t)NR * DD, invdr, tr, DD,
                out, nullptr, nullptr);
        } else {
            reduce_epi_k<1><<<(NR_P * 128 + 255) / 256, 256>>>(
                NR, NR_P, KSPLIT_R, partR, (size_t)NR * DD, invdr, tr, DD,
                nullptr, hrhi, hrlo);

            // bigS: partS = A^T @ gr (1-term BK64, A read transposed, split-K)
            hmma_gemm_k<1, 0, 0, 1, 0><<<dim3(4, NS_P / 128, KSPLIT_S), 256, SMEM_1T64>>>(
                NS, KR_P / 64, Ahi, nullptr, NS_P, grhi, nullptr, DD,
                partS, DD, (size_t)NS * DD);

            // h_s' = relu(invdeg_s * (A^T @ gr) + ts), hi-only
            reduce_epi_k<2><<<(NS_P * 128 + 255) / 256, 256>>>(
                NS, NS_P, KSPLIT_S, partS, (size_t)NS * DD, invds,
                fS + 512, 1024, nullptr, hshi, nullptr);
        }
    }
}

// round 17
// speedup vs baseline: 1.0759x; 1.0368x over previous
#include <cuda_runtime.h>
#include <cuda_fp16.h>
#include <cstdint>

// ---------------------------------------------------------------------------
// Problem constants
// ---------------------------------------------------------------------------
#define NR 20000          // readings
#define NS 5000           // skills
#define DD 512            // embedding dim
#define NL 3              // layers
#define NR_P 20096        // NR padded to 128
#define NS_P 5120         // NS padded to 128
#define KR_P 20032        // NR padded to 64 (K dim of A^T GEMM)
#define COL_CHUNKS 16
#define KSPLIT_R 4        // split-K for A@gs
#define KSPLIT_S 4        // split-K for A^T@gr

// ---------------------------------------------------------------------------
// Device scratch (no cudaMalloc allowed)
// ---------------------------------------------------------------------------
__device__ float g_invdeg_r[NR];
__device__ float g_invdeg_s[NS];
__device__ float g_colpart[COL_CHUNKS * NS];

__device__ __align__(16) __half g_Ahi[(size_t)NR_P * NS_P];
__device__ __align__(16) __half g_hrhi[(size_t)NR_P * DD];
__device__ __align__(16) __half g_hrlo[(size_t)NR_P * DD];
__device__ __align__(16) __half g_hshi[(size_t)NS_P * DD];
__device__ __align__(16) __half g_gshi[(size_t)NS_P * DD];
__device__ __align__(16) __half g_grhi[(size_t)NR_P * DD];
__device__ __align__(16) __half g_WShi[(size_t)NL * DD * 1024];  // [Ws|Vs] hi
__device__ __align__(16) __half g_Wrhi[(size_t)NL * DD * DD];
__device__ __align__(16) __half g_Wrlo[(size_t)NL * DD * DD];
__device__ __align__(16) __half g_Vrhi[(size_t)NL * DD * DD];

__device__ float g_fS[(size_t)NS * 1024];            // [gs | ts], stride 1024
__device__ float g_tr[(size_t)NR * DD];
__device__ float g_partR[(size_t)KSPLIT_R * NR * DD];
__device__ float g_partS[(size_t)KSPLIT_S * NS * DD];

// ---------------------------------------------------------------------------
// PTX helpers
// ---------------------------------------------------------------------------
__device__ __forceinline__ uint32_t smem_u32(const void* p) {
    uint32_t a;
    asm("{ .reg .u64 t; cvta.to.shared.u64 t, %1; cvt.u32.u64 %0, t; }"
        : "=r"(a) : "l"(p));
    return a;
}
__device__ __forceinline__ void cp16(uint32_t dst, const void* src) {
    asm volatile("cp.async.cg.shared.global [%0], [%1], 16;"
                 :: "r"(dst), "l"(src) : "memory");
}
__device__ __forceinline__ void cp_commit() {
    asm volatile("cp.async.commit_group;" ::: "memory");
}
template <int N>
__device__ __forceinline__ void cp_wait() {
    asm volatile("cp.async.wait_group %0;" :: "n"(N) : "memory");
}
__device__ __forceinline__ void ldsm4(uint32_t& r0, uint32_t& r1,
                                      uint32_t& r2, uint32_t& r3, uint32_t a) {
    asm volatile("ldmatrix.sync.aligned.m8n8.x4.shared.b16 {%0,%1,%2,%3}, [%4];"
                 : "=r"(r0), "=r"(r1), "=r"(r2), "=r"(r3) : "r"(a));
}
__device__ __forceinline__ void ldsm4t(uint32_t& r0, uint32_t& r1,
                                       uint32_t& r2, uint32_t& r3, uint32_t a) {
    asm volatile("ldmatrix.sync.aligned.m8n8.x4.trans.shared.b16 {%0,%1,%2,%3}, [%4];"
                 : "=r"(r0), "=r"(r1), "=r"(r2), "=r"(r3) : "r"(a));
}
__device__ __forceinline__ void mma16816(float* d, const uint32_t* a,
                                         const uint32_t* b) {
    asm volatile(
        "mma.sync.aligned.m16n8k16.row.col.f32.f16.f16.f32 "
        "{%0,%1,%2,%3}, {%4,%5,%6,%7}, {%8,%9}, {%0,%1,%2,%3};"
        : "+f"(d[0]), "+f"(d[1]), "+f"(d[2]), "+f"(d[3])
        : "r"(a[0]), "r"(a[1]), "r"(a[2]), "r"(a[3]), "r"(b[0]), "r"(b[1]));
}
// A-normal tile [128m x BKk], MUL=2 for BK32, MUL=1 for BK64.
__device__ __forceinline__ uint32_t swzA(int r, int c16, int mul) {
    return (uint32_t)((c16 << 11) + ((r >> 3) << 7) + (((r + mul * c16) & 7) << 4));
}
// K-major tile [BKk x 128cols] (256B rows): XOR swizzle.
__device__ __forceinline__ uint32_t swz_kn(int r, int c) {
    return (uint32_t)(r * 256 + ((c & 8) << 4) + (((c ^ r) & 7) << 4));
}

#define SMEM_GEMM (3 * 32768)   // 3 stages x 32 KB

// ---------------------------------------------------------------------------
// Stage loaders
// ---------------------------------------------------------------------------
// 1-term BK64 stage: Ahi [128x64] (+0, 16KB) ; Bhi [64x128] (+16384, 16KB)
template <int A_TRANS>
__device__ __forceinline__ void load_stage1(uint32_t sb,
    const __half* __restrict__ Ahi, int lda, int bm,
    const __half* __restrict__ Bhi, int ldb, int bn, int k0, int tid)
{
    #pragma unroll
    for (int i = 0; i < 4; i++) {
        const int idx = tid + i * 256;
        const int r = idx >> 4, c = idx & 15;
        cp16(sb + 16384 + swz_kn(r, c),
             Bhi + (size_t)(k0 + r) * ldb + bn + c * 8);
        if (A_TRANS) {
            cp16(sb + swz_kn(r, c),
                 Ahi + (size_t)(k0 + r) * lda + bm + c * 8);
        } else {
            const int c16 = idx & 7, ra = idx >> 3;
            cp16(sb + swzA(ra, c16, 1),
                 Ahi + (size_t)(bm + ra) * lda + k0 + c16 * 8);
        }
    }
}

// 3-term BK32 stage: Ahi(+0) Alo(+8K) Bhi(+16K) Blo(+24K), each 8 KB
__device__ __forceinline__ void load_stage3(uint32_t sb,
    const __half* __restrict__ Ahi, const __half* __restrict__ Alo, int lda,
    int bm,
    const __half* __restrict__ Bhi, const __half* __restrict__ Blo, int ldb,
    int bn, int k0, int tid)
{
    #pragma unroll
    for (int i = 0; i < 2; i++) {
        const int idx = tid + i * 256;
        const int r = idx >> 4, c = idx & 15;
        const uint32_t so = swz_kn(r, c);
        const size_t bo = (size_t)(k0 + r) * ldb + bn + c * 8;
        cp16(sb + 16384 + so, Bhi + bo);
        cp16(sb + 24576 + so, Blo + bo);
        const int c16 = idx & 3, ra = idx >> 2;
        const uint32_t soA = swzA(ra, c16, 2);
        const size_t ao = (size_t)(bm + ra) * lda + k0 + c16 * 8;
        cp16(sb + soA,        Ahi + ao);
        cp16(sb + 8192 + soA, Alo + ao);
    }
}

// ---------------------------------------------------------------------------
// 1-term mainloop body (device function): accumulates into acc.
// ---------------------------------------------------------------------------
template <int A_TRANS>
__device__ __forceinline__ void gemm1_loop(uint32_t smb, int kc0, int kcn,
    const __half* __restrict__ Ahi, int lda, int bm,
    const __half* __restrict__ Bhi, int ldb, int bn,
    int tid, int lane, int warp_m, int warp_n, float acc[4][4][4])
{
    constexpr int STAGE = 32768, NST = 3;
    #pragma unroll
    for (int s = 0; s < NST - 1; s++) {
        if (s < kcn)
            load_stage1<A_TRANS>(smb + s * STAGE, Ahi, lda, bm,
                                 Bhi, ldb, bn, (kc0 + s) * 64, tid);
        cp_commit();
    }
    const int aN_r  = warp_m * 64 + (lane & 15);
    const int aN_ch = lane >> 4;
    const int aT_r  = (lane & 7) + ((lane >> 4) << 3);
    const int aT_cb = warp_m * 8 + ((lane >> 3) & 1);
    const int b_r   = lane & 15;
    const int b_cb  = warp_n * 4 + (lane >> 4);

    for (int ci = 0; ci < kcn; ci++) {
        cp_wait<NST - 2>();
        __syncthreads();
        if (ci + NST - 1 < kcn)
            load_stage1<A_TRANS>(smb + ((ci + NST - 1) % NST) * STAGE,
                                 Ahi, lda, bm, Bhi, ldb, bn,
                                 (kc0 + ci + NST - 1) * 64, tid);
        cp_commit();

        const uint32_t sb = smb + (ci % NST) * STAGE;
        #pragma unroll
        for (int ks = 0; ks < 4; ks++) {
            uint32_t ah[4][4], bh[2][4];
            #pragma unroll
            for (int mf = 0; mf < 4; mf++) {
                if (A_TRANS) {
                    const uint32_t ad =
                        sb + swz_kn(ks * 16 + aT_r, aT_cb + mf * 2);
                    ldsm4t(ah[mf][0], ah[mf][1], ah[mf][2], ah[mf][3], ad);
                } else {
                    const uint32_t ad =
                        sb + swzA(aN_r + mf * 16, ks * 2 + aN_ch, 1);
                    ldsm4(ah[mf][0], ah[mf][1], ah[mf][2], ah[mf][3], ad);
                }
            }
            #pragma unroll
            for (int np = 0; np < 2; np++) {
                const uint32_t bd =
                    sb + 16384 + swz_kn(ks * 16 + b_r, b_cb + np * 2);
                ldsm4t(bh[np][0], bh[np][1], bh[np][2], bh[np][3], bd);
                #pragma unroll
                for (int mf = 0; mf < 4; mf++) {
                    mma16816(acc[mf][np * 2],     ah[mf], &bh[np][0]);
                    mma16816(acc[mf][np * 2 + 1], ah[mf], &bh[np][2]);
                }
            }
        }
    }
}

// ---------------------------------------------------------------------------
// Combined small-GEMM kernel: fS (1-term fp32, ld 1024) | gr (1-term fp16) |
// tr (3-term fp32), flat block decode. K=512.
// ---------------------------------------------------------------------------
__global__ void __launch_bounds__(256, 2)
small_combo_k(int c1, int n1tiles,
              const __half* __restrict__ hshi,
              const __half* __restrict__ WShi,     // [512 x 1024], ld 1024
              float* __restrict__ fS,              // [NS x 1024], ld 1024
              int c2,
              const __half* __restrict__ hrhi, const __half* __restrict__ hrlo,
              const __half* __restrict__ Vrhi,     // [512 x 512]
              __half* __restrict__ grhi,
              const __half* __restrict__ Wrhi, const __half* __restrict__ Wrlo,
              float* __restrict__ tr)
{
    extern __shared__ char sm[];
    const uint32_t smb = smem_u32(sm);
    const int tid  = threadIdx.x;
    const int wid  = tid >> 5;
    const int lane = tid & 31;
    const int warp_m = wid & 1;
    const int warp_n = wid >> 1;
    const int id = blockIdx.x;

    float acc[4][4][4];
    #pragma unroll
    for (int mf = 0; mf < 4; mf++)
        #pragma unroll
        for (int nt = 0; nt < 4; nt++)
            #pragma unroll
            for (int i = 0; i < 4; i++) acc[mf][nt][i] = 0.f;

    const int row_in = lane >> 2;
    const int col_in = (lane & 3) * 2;

    if (id < c1 + c2) {
        // ---------------- 1-term problems ----------------
        int bm, bn, M, lda, ldb;
        const __half *Ah, *Bh;
        bool outf32;
        if (id < c1) {
            bn = (id % n1tiles) * 128; bm = (id / n1tiles) * 128;
            M = NS; Ah = hshi; lda = DD; Bh = WShi; ldb = 1024;   // ld FIXED
            outf32 = true;
        } else {
            const int id2 = id - c1;
            bn = (id2 & 3) * 128; bm = (id2 >> 2) * 128;
            M = NR_P; Ah = hrhi; lda = DD; Bh = Vrhi; ldb = DD;
            outf32 = false;
        }
        gemm1_loop<0>(smb, 0, 8, Ah, lda, bm, Bh, ldb, bn,
                      tid, lane, warp_m, warp_n, acc);

        #pragma unroll
        for (int mf = 0; mf < 4; mf++) {
            #pragma unroll
            for (int h2 = 0; h2 < 2; h2++) {
                const int m = bm + warp_m * 64 + mf * 16 + row_in + h2 * 8;
                if (m >= M) continue;
                #pragma unroll
                for (int nt = 0; nt < 4; nt++) {
                    const int n = bn + warp_n * 32 + nt * 8 + col_in;
                    const float v0 = acc[mf][nt][h2 * 2 + 0];
                    const float v1 = acc[mf][nt][h2 * 2 + 1];
                    if (outf32) {
                        float2 o; o.x = v0; o.y = v1;
                        *reinterpret_cast<float2*>(
                            fS + (size_t)m * 1024 + n) = o;        // ld FIXED
                    } else {
                        *reinterpret_cast<__half2*>(grhi + (size_t)m * DD + n) =
                            __halves2half2(__float2half_rn(v0),
                                           __float2half_rn(v1));
                    }
                }
            }
        }
    } else {
        // ---------------- 3-term tr = h_r @ Wr ----------------
        constexpr int STAGE = 32768, NST = 3, Kc = 16;
        const int id3 = id - c1 - c2;
        const int bn = (id3 & 3) * 128;
        const int bm = (id3 >> 2) * 128;

        #pragma unroll
        for (int s = 0; s < NST - 1; s++) {
            load_stage3(smb + s * STAGE, hrhi, hrlo, DD, bm,
                        Wrhi, Wrlo, DD, bn, s * 32, tid);
            cp_commit();
        }
        const int aN_r  = warp_m * 64 + (lane & 15);
        const int aN_ch = lane >> 4;
        const int b_r   = lane & 15;
        const int b_cb  = warp_n * 4 + (lane >> 4);

        for (int ci = 0; ci < Kc; ci++) {
            cp_wait<NST - 2>();
            __syncthreads();
            if (ci + NST - 1 < Kc)
                load_stage3(smb + ((ci + NST - 1) % NST) * STAGE,
                            hrhi, hrlo, DD, bm, Wrhi, Wrlo, DD, bn,
                            (ci + NST - 1) * 32, tid);
            cp_commit();

            const uint32_t sb = smb + (ci % NST) * STAGE;
            #pragma unroll
            for (int ks = 0; ks < 2; ks++) {
                uint32_t ah[4][4], al[4][4], bh[2][4], bl[2][4];
                #pragma unroll
                for (int mf = 0; mf < 4; mf++) {
                    const uint32_t ad =
                        sb + swzA(aN_r + mf * 16, ks * 2 + aN_ch, 2);
                    ldsm4(ah[mf][0], ah[mf][1], ah[mf][2], ah[mf][3], ad);
                    ldsm4(al[mf][0], al[mf][1], al[mf][2], al[mf][3], ad + 8192);
                }
                #pragma unroll
                for (int np = 0; np < 2; np++) {
                    const uint32_t bd =
                        sb + 16384 + swz_kn(ks * 16 + b_r, b_cb + np * 2);
                    ldsm4t(bh[np][0], bh[np][1], bh[np][2], bh[np][3], bd);
                    ldsm4t(bl[np][0], bl[np][1], bl[np][2], bl[np][3], bd + 8192);
                }
                #pragma unroll
                for (int mf = 0; mf < 4; mf++) {
                    #pragma unroll
                    for (int np = 0; np < 2; np++) {
                        mma16816(acc[mf][np * 2],     ah[mf], &bh[np][0]);
                        mma16816(acc[mf][np * 2 + 1], ah[mf], &bh[np][2]);
                        mma16816(acc[mf][np * 2],     ah[mf], &bl[np][0]);
                        mma16816(acc[mf][np * 2 + 1], ah[mf], &bl[np][2]);
                        mma16816(acc[mf][np * 2],     al[mf], &bh[np][0]);
                        mma16816(acc[mf][np * 2 + 1], al[mf], &bh[np][2]);
                    }
                }
            }
        }

        #pragma unroll
        for (int mf = 0; mf < 4; mf++) {
            #pragma unroll
            for (int h2 = 0; h2 < 2; h2++) {
                const int m = bm + warp_m * 64 + mf * 16 + row_in + h2 * 8;
                if (m >= NR) continue;
                #pragma unroll
                for (int nt = 0; nt < 4; nt++) {
                    const int n = bn + warp_n * 32 + nt * 8 + col_in;
                    float2 o;
                    o.x = acc[mf][nt][h2 * 2 + 0];
                    o.y = acc[mf][nt][h2 * 2 + 1];
                    *reinterpret_cast<float2*>(tr + (size_t)m * DD + n) = o;
                }
            }
        }
    }
}

// ---------------------------------------------------------------------------
// Combined big-GEMM kernel: bigR (A @ gs) then bigS (A^T @ gr), flat decode.
// ---------------------------------------------------------------------------
__global__ void __launch_bounds__(256, 2)
big_combo_k(int cR,
            const __half* __restrict__ Ahi,
            const __half* __restrict__ gshi, float* __restrict__ partR,
            const __half* __restrict__ grhi, float* __restrict__ partS)
{
    extern __shared__ char sm[];
    const uint32_t smb = smem_u32(sm);
    const int tid  = threadIdx.x;
    const int wid  = tid >> 5;
    const int lane = tid & 31;
    const int warp_m = wid & 1;
    const int warp_n = wid >> 1;
    const int id = blockIdx.x;

    float acc[4][4][4];
    #pragma unroll
    for (int mf = 0; mf < 4; mf++)
        #pragma unroll
        for (int nt = 0; nt < 4; nt++)
            #pragma unroll
            for (int i = 0; i < 4; i++) acc[mf][nt][i] = 0.f;

    const int row_in = lane >> 2;
    const int col_in = (lane & 3) * 2;

    if (id < cR) {
        const int xy = id % (4 * (NR_P / 128));
        const int p  = id / (4 * (NR_P / 128));
        const int bn = (xy & 3) * 128;
        const int bm = (xy >> 2) * 128;
        const int Kc = NS_P / 64;                 // 80
        const int kbase = Kc / KSPLIT_R, krem = Kc - kbase * KSPLIT_R;
        const int kc0 = p * kbase + (p < krem ? p : krem);
        const int kcn = kbase + (p < krem ? 1 : 0);

        gemm1_loop<0>(smb, kc0, kcn, Ahi, NS_P, bm, gshi, DD, bn,
                      tid, lane, warp_m, warp_n, acc);

        float* C = partR + (size_t)p * NR * DD;
        #pragma unroll
        for (int mf = 0; mf < 4; mf++) {
            #pragma unroll
            for (int h2 = 0; h2 < 2; h2++) {
                const int m = bm + warp_m * 64 + mf * 16 + row_in + h2 * 8;
                if (m >= NR) continue;
                #pragma unroll
                for (int nt = 0; nt < 4; nt++) {
                    const int n = bn + warp_n * 32 + nt * 8 + col_in;
                    float2 o;
                    o.x = acc[mf][nt][h2 * 2 + 0];
                    o.y = acc[mf][nt][h2 * 2 + 1];
                    *reinterpret_cast<float2*>(C + (size_t)m * DD + n) = o;
                }
            }
        }
    } else {
        const int id2 = id - cR;
        const int xy = id2 % (4 * (NS_P / 128));
        const int p  = id2 / (4 * (NS_P / 128));
        const int bn = (xy & 3) * 128;
        const int bm = (xy >> 2) * 128;
        const int Kc = KR_P / 64;                 // 313
        const int kbase = Kc / KSPLIT_S, krem = Kc - kbase * KSPLIT_S;
        const int kc0 = p * kbase + (p < krem ? p : krem);
        const int kcn = kbase + (p < krem ? 1 : 0);

        gemm1_loop<1>(smb, kc0, kcn, Ahi, NS_P, bm, grhi, DD, bn,
                      tid, lane, warp_m, warp_n, acc);

        float* C = partS + (size_t)p * NS * DD;
        #pragma unroll
        for (int mf = 0; mf < 4; mf++) {
            #pragma unroll
            for (int h2 = 0; h2 < 2; h2++) {
                const int m = bm + warp_m * 64 + mf * 16 + row_in + h2 * 8;
                if (m >= NS) continue;
                #pragma unroll
                for (int nt = 0; nt < 4; nt++) {
                    const int n = bn + warp_n * 32 + nt * 8 + col_in;
                    float2 o;
                    o.x = acc[mf][nt][h2 * 2 + 0];
                    o.y = acc[mf][nt][h2 * 2 + 1];
                    *reinterpret_cast<float2*>(C + (size_t)m * DD + n) = o;
                }
            }
        }
    }
}

// ---------------------------------------------------------------------------
// Fused reduce + epilogue for both sides.
// ---------------------------------------------------------------------------
template <int LAST>
__global__ void reduce_both_k(const float* __restrict__ partR,
                              const float* __restrict__ invdr,
                              const float* __restrict__ tr,
                              float* __restrict__ out32,
                              __half* __restrict__ hrhi, __half* __restrict__ hrlo,
                              const float* __restrict__ partS,
                              const float* __restrict__ invds,
                              const float* __restrict__ fS,
                              __half* __restrict__ hshi)
{
    const int RCNT = NR_P * 128;
    int idx = blockIdx.x * 256 + threadIdx.x;
    if (idx < RCNT) {
        const int m = idx >> 7, q = (idx & 127) << 2;
        float4 o = make_float4(0.f, 0.f, 0.f, 0.f);
        if (m < NR) {
            float4 s = make_float4(0.f, 0.f, 0.f, 0.f);
            #pragma unroll
            for (int pp = 0; pp < KSPLIT_R; pp++) {
                const float4 v = *reinterpret_cast<const float4*>(
                    partR + (size_t)pp * NR * DD + (size_t)m * DD + q);
                s.x += v.x; s.y += v.y; s.z += v.z; s.w += v.w;
            }
            const float sc = invdr[m];
            const float4 a = *reinterpret_cast<const float4*>(
                tr + (size_t)m * DD + q);
            o.x = fmaxf(fmaf(sc, s.x, a.x), 0.f);
            o.y = fmaxf(fmaf(sc, s.y, a.y), 0.f);
            o.z = fmaxf(fmaf(sc, s.z, a.z), 0.f);
            o.w = fmaxf(fmaf(sc, s.w, a.w), 0.f);
        }
        if (LAST) {
            if (m < NR)
                *reinterpret_cast<float4*>(out32 + (size_t)m * DD + q) = o;
        } else {
            __half h0 = __float2half_rn(o.x), h1 = __float2half_rn(o.y);
            __half h2 = __float2half_rn(o.z), h3 = __float2half_rn(o.w);
            const size_t off = (size_t)m * DD + q;
            *reinterpret_cast<__half2*>(hrhi + off)     = __halves2half2(h0, h1);
            *reinterpret_cast<__half2*>(hrhi + off + 2) = __halves2half2(h2, h3);
            *reinterpret_cast<__half2*>(hrlo + off) = __halves2half2(
                __float2half_rn(o.x - __half2float(h0)),
                __float2half_rn(o.y - __half2float(h1)));
            *reinterpret_cast<__half2*>(hrlo + off + 2) = __halves2half2(
                __float2half_rn(o.z - __half2float(h2)),
                __float2half_rn(o.w - __half2float(h3)));
        }
    } else if (!LAST) {
        idx -= RCNT;
        if (idx >= NS_P * 128) return;
        const int m = idx >> 7, q = (idx & 127) << 2;
        float4 o = make_float4(0.f, 0.f, 0.f, 0.f);
        if (m < NS) {
            float4 s = make_float4(0.f, 0.f, 0.f, 0.f);
            #pragma unroll
            for (int pp = 0; pp < KSPLIT_S; pp++) {
                const float4 v = *reinterpret_cast<const float4*>(
                    partS + (size_t)pp * NS * DD + (size_t)m * DD + q);
                s.x += v.x; s.y += v.y; s.z += v.z; s.w += v.w;
            }
            const float sc = invds[m];
            const float4 a = *reinterpret_cast<const float4*>(
                fS + (size_t)m * 1024 + 512 + q);
            o.x = fmaxf(fmaf(sc, s.x, a.x), 0.f);
            o.y = fmaxf(fmaf(sc, s.y, a.y), 0.f);
            o.z = fmaxf(fmaf(sc, s.z, a.z), 0.f);
            o.w = fmaxf(fmaf(sc, s.w, a.w), 0.f);
        }
        const size_t off = (size_t)m * DD + q;
        *reinterpret_cast<__half2*>(hshi + off) =
            __halves2half2(__float2half_rn(o.x), __float2half_rn(o.y));
        *reinterpret_cast<__half2*>(hshi + off + 2) =
            __halves2half2(__float2half_rn(o.z), __float2half_rn(o.w));
    }
}

// ---------------------------------------------------------------------------
// Conversions
// ---------------------------------------------------------------------------
__global__ void splitA_hi_k(const float* __restrict__ A,
                            __half* __restrict__ hi,
                            float* __restrict__ invdeg)
{
    const int r = blockIdx.x;           // 0..NR_P-1
    const bool real = (r < NR);
    const int tid = threadIdx.x;        // 256
    float acc = 0.f;
    for (int c4 = tid; c4 < NS_P / 4; c4 += 256) {
        float4 v = make_float4(0.f, 0.f, 0.f, 0.f);
        if (real && c4 < NS / 4)
            v = *reinterpret_cast<const float4*>(A + (size_t)r * NS + c4 * 4);
        acc += (v.x + v.y) + (v.z + v.w);
        const size_t o = (size_t)r * NS_P + c4 * 4;
        *reinterpret_cast<__half2*>(hi + o) =
            __halves2half2(__float2half_rn(v.x), __float2half_rn(v.y));
        *reinterpret_cast<__half2*>(hi + o + 2) =
            __halves2half2(__float2half_rn(v.z), __float2half_rn(v.w));
    }
    #pragma unroll
    for (int off = 16; off; off >>= 1) acc += __shfl_down_sync(0xffffffffu, acc, off);
    __shared__ float ws[8];
    if ((tid & 31) == 0) ws[tid >> 5] = acc;
    __syncthreads();
    if (tid == 0 && real) {
        float s = 0.f;
        #pragma unroll
        for (int w = 0; w < 8; w++) s += ws[w];
        invdeg[r] = 1.f / (s + 1e-6f);
    }
}

__global__ void split_cols_k(const float* __restrict__ in, int ld, int col0,
                             __half* __restrict__ hi, __half* __restrict__ lo,
                             int M)
{
    const int r = blockIdx.x;
    const int c = threadIdx.x * 4;
    float4 v = make_float4(0.f, 0.f, 0.f, 0.f);
    if (r < M)
        v = *reinterpret_cast<const float4*>(in + (size_t)r * ld + col0 + c);
    __half h0 = __float2half_rn(v.x), h1 = __float2half_rn(v.y);
    __half h2 = __float2half_rn(v.z), h3 = __float2half_rn(v.w);
    const size_t o = (size_t)r * DD + c;
    *reinterpret_cast<__half2*>(hi + o)     = __halves2half2(h0, h1);
    *reinterpret_cast<__half2*>(hi + o + 2) = __halves2half2(h2, h3);
    *reinterpret_cast<__half2*>(lo + o) = __halves2half2(
        __float2half_rn(v.x - __half2float(h0)),
        __float2half_rn(v.y - __half2float(h1)));
    *reinterpret_cast<__half2*>(lo + o + 2) = __halves2half2(
        __float2half_rn(v.z - __half2float(h2)),
        __float2half_rn(v.w - __half2float(h3)));
}

__global__ void split_cols_hi_k(const float* __restrict__ in, int ld, int col0,
                                __half* __restrict__ hi, int M)
{
    const int r = blockIdx.x;
    const int c = threadIdx.x * 4;
    float4 v = make_float4(0.f, 0.f, 0.f, 0.f);
    if (r < M)
        v = *reinterpret_cast<const float4*>(in + (size_t)r * ld + col0 + c);
    const size_t o = (size_t)r * DD + c;
    *reinterpret_cast<__half2*>(hi + o) =
        __halves2half2(__float2half_rn(v.x), __float2half_rn(v.y));
    *reinterpret_cast<__half2*>(hi + o + 2) =
        __halves2half2(__float2half_rn(v.z), __float2half_rn(v.w));
}

__global__ void splitW_hi_k(const float* __restrict__ W,
                            const float* __restrict__ V,
                            __half* __restrict__ hi)
{
    const int row = blockIdx.x;           // 0 .. NL*512-1
    const int l = row >> 9, k = row & 511;
    const int n = threadIdx.x * 4;        // 256 threads -> 1024 cols
    const float* src = (n < 512) ? (W + ((size_t)l * DD + k) * DD + n)
                                 : (V + ((size_t)l * DD + k) * DD + n - 512);
    float4 v = *reinterpret_cast<const float4*>(src);
    const size_t o = (size_t)row * 1024 + n;
    *reinterpret_cast<__half2*>(hi + o) =
        __halves2half2(__float2half_rn(v.x), __float2half_rn(v.y));
    *reinterpret_cast<__half2*>(hi + o + 2) =
        __halves2half2(__float2half_rn(v.z), __float2half_rn(v.w));
}

// ---------------------------------------------------------------------------
// Column degrees
// ---------------------------------------------------------------------------
__global__ void colsum_part_k(const float* __restrict__ A, float* __restrict__ part)
{
    int s = blockIdx.x * blockDim.x + threadIdx.x;
    if (s >= NS) return;
    int chunk = blockIdx.y;
    const int rows = NR / COL_CHUNKS;
    const float* p = A + (size_t)(chunk * rows) * NS + s;
    float acc = 0.f;
    for (int r = 0; r < rows; r++) acc += p[(size_t)r * NS];
    part[chunk * NS + s] = acc;
}
__global__ void colsum_fin_k(const float* __restrict__ part, float* __restrict__ invdeg)
{
    int s = blockIdx.x * blockDim.x + threadIdx.x;
    if (s >= NS) return;
    float acc = 0.f;
    #pragma unroll
    for (int c = 0; c < COL_CHUNKS; c++) acc += part[c * NS + s];
    invdeg[s] = 1.f / (acc + 1e-6f);
}

// ---------------------------------------------------------------------------
// Host orchestration
// ---------------------------------------------------------------------------
extern "C" void kernel_launch(void* const* d_in, const int* in_sizes, int n_in,
                              void* d_out, int out_size)
{
    const float* h_s_in = (const float*)d_in[0];  // [NS, DD]
    const float* A      = (const float*)d_in[1];  // [NR, NS]
    const float* r_emb  = (const float*)d_in[2];  // [NR, DD]
    const float* Wr     = (const float*)d_in[3];  // [NL, DD, DD]
    const float* Ws     = (const float*)d_in[4];
    const float* Vr     = (const float*)d_in[5];
    const float* Vs     = (const float*)d_in[6];
    float* out = (float*)d_out;                   // [NR, DD]

    cudaFuncSetAttribute((const void*)small_combo_k,
                         cudaFuncAttributeMaxDynamicSharedMemorySize, SMEM_GEMM);
    cudaFuncSetAttribute((const void*)big_combo_k,
                         cudaFuncAttributeMaxDynamicSharedMemorySize, SMEM_GEMM);

    float *invdr, *invds, *colpart, *fS, *tr, *partR, *partS;
    __half *Ahi, *hrhi, *hrlo, *hshi, *gshi, *grhi, *WShi, *Wrhi, *Wrlo, *Vrhi;
    cudaGetSymbolAddress((void**)&invdr,   g_invdeg_r);
    cudaGetSymbolAddress((void**)&invds,   g_invdeg_s);
    cudaGetSymbolAddress((void**)&colpart, g_colpart);
    cudaGetSymbolAddress((void**)&fS,    g_fS);
    cudaGetSymbolAddress((void**)&tr,    g_tr);
    cudaGetSymbolAddress((void**)&partR, g_partR);
    cudaGetSymbolAddress((void**)&partS, g_partS);
    cudaGetSymbolAddress((void**)&Ahi,  g_Ahi);
    cudaGetSymbolAddress((void**)&hrhi, g_hrhi);
    cudaGetSymbolAddress((void**)&hrlo, g_hrlo);
    cudaGetSymbolAddress((void**)&hshi, g_hshi);
    cudaGetSymbolAddress((void**)&gshi, g_gshi);
    cudaGetSymbolAddress((void**)&grhi, g_grhi);
    cudaGetSymbolAddress((void**)&WShi, g_WShi);
    cudaGetSymbolAddress((void**)&Wrhi, g_Wrhi);
    cudaGetSymbolAddress((void**)&Wrlo, g_Wrlo);
    cudaGetSymbolAddress((void**)&Vrhi, g_Vrhi);

    // --- one-time conversions & degrees ---
    split_cols_hi_k<<<NS_P, 128>>>(h_s_in, DD, 0, hshi, NS);
    splitW_hi_k<<<NL * DD, 256>>>(Ws, Vs, WShi);
    split_cols_k<<<NL * DD, 128>>>(Wr, DD, 0, Wrhi, Wrlo, NL * DD);
    split_cols_hi_k<<<NL * DD, 128>>>(Vr, DD, 0, Vrhi, NL * DD);
    split_cols_k<<<NR_P, 128>>>(r_emb, DD, 0, hrhi, hrlo, NR);
    splitA_hi_k<<<NR_P, 256>>>(A, Ahi, invdr);
    colsum_part_k<<<dim3((NS + 255) / 256, COL_CHUNKS), 256>>>(A, colpart);
    colsum_fin_k<<<(NS + 255) / 256, 256>>>(colpart, invds);

    for (int l = 0; l < NL; l++) {
        const bool last = (l == NL - 1);
        const int n1tiles = last ? 4 : 8;         // fS width tiles used
        const int c1 = n1tiles * (NS_P / 128);
        const int c2 = last ? 0 : 4 * (NR_P / 128);
        const int c3 = 4 * (NR_P / 128);          // tr tiles

        // fS | gr | tr  in one launch
        small_combo_k<<<c1 + c2 + c3, 256, SMEM_GEMM>>>(
            c1, n1tiles, hshi, WShi + (size_t)l * DD * 1024, fS,
            c2, hrhi, hrlo, Vrhi + (size_t)l * DD * DD, grhi,
            Wrhi + (size_t)l * DD * DD, Wrlo + (size_t)l * DD * DD, tr);

        // gs -> fp16 hi (aggregation operand); fS stride is always 1024
        split_cols_hi_k<<<NS_P, 128>>>(fS, 1024, 0, gshi, NS);

        // bigR (+ bigS if !last) in one launch
        const int cR = 4 * (NR_P / 128) * KSPLIT_R;
        const int cS = last ? 0 : 4 * (NS_P / 128) * KSPLIT_S;
        big_combo_k<<<cR + cS, 256, SMEM_GEMM>>>(
            cR, Ahi, gshi, partR, grhi, partS);

        // fused reduce + epilogue for both sides
        if (last) {
            reduce_both_k<1><<<(NR_P * 128 + 255) / 256, 256>>>(
                partR, invdr, tr, out, nullptr, nullptr,
                nullptr, nullptr, nullptr, nullptr);
        } else {
            reduce_both_k<0><<<((NR_P + NS_P) * 128 + 255) / 256, 256>>>(
                partR, invdr, tr, nullptr, hrhi, hrlo,
                partS, invds, fS, hshi);
        }
    }
}